// round 6
// baseline (speedup 1.0000x reference)
#include <cuda_runtime.h>
#include <math.h>
#include <float.h>
#include <stdint.h>

// Problem constants
#define Bn   4
#define Dd   256
#define Nn   2048
#define Mm   2048
#define Hh   4
#define DIMh 64

// Scratch (allocation-free: __device__ globals)
__device__ float g_q[Bn * Dd * Nn];
__device__ float g_k[Bn * Dd * Mm];
__device__ float g_v[Bn * Dd * Mm];
__device__ float g_msg[Bn * Dd * Nn];
__device__ float g_message[Bn * Dd * Nn];
__device__ float g_h[Bn * 2 * Dd * Nn];

// ---------------------------------------------------------------------------
// tf32 helpers
// ---------------------------------------------------------------------------
__device__ __forceinline__ uint32_t f2tf(float x)
{
    uint32_t r;
    asm("cvt.rna.tf32.f32 %0, %1;" : "=r"(r) : "f"(x));
    return r;
}
__device__ __forceinline__ void split_tf32(float x, uint32_t& hi, uint32_t& lo)
{
    hi = f2tf(x);
    lo = f2tf(x - __uint_as_float(hi));
}

__device__ __forceinline__ void mma_tf32(float (&d)[4],
                                         uint32_t a0, uint32_t a1, uint32_t a2, uint32_t a3,
                                         uint32_t b0, uint32_t b1)
{
    asm volatile(
        "mma.sync.aligned.m16n8k8.row.col.f32.tf32.tf32.f32 "
        "{%0,%1,%2,%3}, {%4,%5,%6,%7}, {%8,%9}, {%0,%1,%2,%3};\n"
        : "+f"(d[0]), "+f"(d[1]), "+f"(d[2]), "+f"(d[3])
        : "r"(a0), "r"(a1), "r"(a2), "r"(a3), "r"(b0), "r"(b1));
}

__device__ __forceinline__ void mma3(float (&d)[4],
                                     const uint32_t (&ah)[4], const uint32_t (&al)[4],
                                     const uint32_t (&bh)[2], const uint32_t (&bl)[2])
{
    mma_tf32(d, al[0], al[1], al[2], al[3], bh[0], bh[1]);
    mma_tf32(d, ah[0], ah[1], ah[2], ah[3], bl[0], bl[1]);
    mma_tf32(d, ah[0], ah[1], ah[2], ah[3], bh[0], bh[1]);
}

#define SM_STRIDE 136   // gemm tiles: 128 cols + 8 pad (conflict-free fragments)
#define AT_STRIDE 72    // attention tiles: 64 cols + 8 pad

// ---------------------------------------------------------------------------
// Generic per-batch 1x1-conv GEMM via 3xTF32 mma (unchanged from R5):
//   Y[b,o,n] = sum_c W[o,c] * X[b,c,n] + bias[o]
// ---------------------------------------------------------------------------
template<int OUTC, int INC, bool CONCAT, bool BNRELU>
__global__ void __launch_bounds__(256)
gemm_mma(const float* __restrict__ W, const float* __restrict__ bias,
         const float* __restrict__ X0, const float* __restrict__ X1,
         float* __restrict__ Y,
         const float* __restrict__ gamma, const float* __restrict__ beta,
         const float* __restrict__ rmean, const float* __restrict__ rvar)
{
    extern __shared__ uint32_t dsm[];
    uint32_t (*AsH)[SM_STRIDE] = (uint32_t(*)[SM_STRIDE])(dsm);
    uint32_t (*AsL)[SM_STRIDE] = (uint32_t(*)[SM_STRIDE])(dsm + 32 * SM_STRIDE);
    uint32_t (*BsH)[SM_STRIDE] = (uint32_t(*)[SM_STRIDE])(dsm + 64 * SM_STRIDE);
    uint32_t (*BsL)[SM_STRIDE] = (uint32_t(*)[SM_STRIDE])(dsm + 96 * SM_STRIDE);

    const int tid = threadIdx.x;
    const int n0 = blockIdx.x * 128;
    const int o0 = blockIdx.y * 128;
    const int b  = blockIdx.z;
    const int XC = CONCAT ? (INC / 2) : INC;
    const float* x0 = X0 + (size_t)b * XC * Nn;
    const float* x1 = CONCAT ? (X1 + (size_t)b * XC * Nn) : nullptr;

    const int w      = tid >> 5;
    const int lane   = tid & 31;
    const int g      = lane >> 2;
    const int tg     = lane & 3;
    const int warp_m = w >> 2;
    const int warp_n = w & 3;

    float acc[4][4][4] = {};

    const int a_row  = tid >> 1;
    const int a_half = tid & 1;
    const int b_row  = tid >> 3;
    const int b_col  = (tid & 7) * 16;

    for (int c0 = 0; c0 < INC; c0 += 32) {
        {
            const float* wp = W + (size_t)(o0 + a_row) * INC + c0 + a_half * 16;
            #pragma unroll
            for (int q = 0; q < 4; q++) {
                float4 v4 = *(const float4*)(wp + q * 4);
                int cl = a_half * 16 + q * 4;
                uint32_t h0,l0,h1,l1,h2,l2,h3,l3;
                split_tf32(v4.x, h0, l0); split_tf32(v4.y, h1, l1);
                split_tf32(v4.z, h2, l2); split_tf32(v4.w, h3, l3);
                AsH[cl+0][a_row]=h0; AsL[cl+0][a_row]=l0;
                AsH[cl+1][a_row]=h1; AsL[cl+1][a_row]=l1;
                AsH[cl+2][a_row]=h2; AsL[cl+2][a_row]=l2;
                AsH[cl+3][a_row]=h3; AsL[cl+3][a_row]=l3;
            }
        }
        {
            int c = c0 + b_row;
            const float* xp;
            if (!CONCAT || c < INC / 2) xp = x0 + (size_t)c * Nn + n0 + b_col;
            else                        xp = x1 + (size_t)(c - INC / 2) * Nn + n0 + b_col;
            #pragma unroll
            for (int q = 0; q < 4; q++) {
                float4 v4 = *(const float4*)(xp + q * 4);
                int cc = b_col + q * 4;
                uint32_t h,l;
                split_tf32(v4.x, h, l); BsH[b_row][cc+0]=h; BsL[b_row][cc+0]=l;
                split_tf32(v4.y, h, l); BsH[b_row][cc+1]=h; BsL[b_row][cc+1]=l;
                split_tf32(v4.z, h, l); BsH[b_row][cc+2]=h; BsL[b_row][cc+2]=l;
                split_tf32(v4.w, h, l); BsH[b_row][cc+3]=h; BsL[b_row][cc+3]=l;
            }
        }
        __syncthreads();

        #pragma unroll
        for (int ks = 0; ks < 4; ks++) {
            const int kb = ks * 8;
            uint32_t ah[4][4], al[4][4], bh[4][2], bl[4][2];
            #pragma unroll
            for (int mt = 0; mt < 4; mt++) {
                int m = warp_m * 64 + mt * 16;
                ah[mt][0]=AsH[kb+tg  ][m+g  ]; al[mt][0]=AsL[kb+tg  ][m+g  ];
                ah[mt][1]=AsH[kb+tg  ][m+g+8]; al[mt][1]=AsL[kb+tg  ][m+g+8];
                ah[mt][2]=AsH[kb+tg+4][m+g  ]; al[mt][2]=AsL[kb+tg+4][m+g  ];
                ah[mt][3]=AsH[kb+tg+4][m+g+8]; al[mt][3]=AsL[kb+tg+4][m+g+8];
            }
            #pragma unroll
            for (int nt = 0; nt < 4; nt++) {
                int n = warp_n * 32 + nt * 8 + g;
                bh[nt][0]=BsH[kb+tg  ][n]; bl[nt][0]=BsL[kb+tg  ][n];
                bh[nt][1]=BsH[kb+tg+4][n]; bl[nt][1]=BsL[kb+tg+4][n];
            }
            #pragma unroll
            for (int mt = 0; mt < 4; mt++)
                #pragma unroll
                for (int nt = 0; nt < 4; nt++)
                    mma3(acc[mt][nt], ah[mt], al[mt], bh[nt], bl[nt]);
        }
        __syncthreads();
    }

    float* yb = Y + (size_t)b * OUTC * Nn;
    #pragma unroll
    for (int mt = 0; mt < 4; mt++) {
        int r0 = o0 + warp_m * 64 + mt * 16 + g;
        int r1 = r0 + 8;
        float bv0 = bias[r0], bv1 = bias[r1];
        float sc0 = 1.f, sh0 = 0.f, sc1 = 1.f, sh1 = 0.f;
        if (BNRELU) {
            float rs0 = rsqrtf(rvar[r0] + 1e-3f);
            sc0 = gamma[r0] * rs0; sh0 = beta[r0] - rmean[r0] * sc0;
            float rs1 = rsqrtf(rvar[r1] + 1e-3f);
            sc1 = gamma[r1] * rs1; sh1 = beta[r1] - rmean[r1] * sc1;
        }
        #pragma unroll
        for (int nt = 0; nt < 4; nt++) {
            int n = n0 + warp_n * 32 + nt * 8 + 2 * tg;
            float t0 = acc[mt][nt][0] + bv0;
            float t1 = acc[mt][nt][1] + bv0;
            float t2 = acc[mt][nt][2] + bv1;
            float t3 = acc[mt][nt][3] + bv1;
            if (BNRELU) {
                t0 = fmaxf(t0 * sc0 + sh0, 0.f);
                t1 = fmaxf(t1 * sc0 + sh0, 0.f);
                t2 = fmaxf(t2 * sc1 + sh1, 0.f);
                t3 = fmaxf(t3 * sc1 + sh1, 0.f);
            }
            *(float2*)&yb[(size_t)r0 * Nn + n] = make_float2(t0, t1);
            *(float2*)&yb[(size_t)r1 * Nn + n] = make_float2(t2, t3);
        }
    }
}

// ---------------------------------------------------------------------------
// Fused flash attention (3xTF32):
//   per (b,h): msg[:, n] = softmax_m( mask ? q·k/8 : -inf ) · v
// Block: 64 queries (n), head-dim 64 resident; m streamed in tiles of 64.
// 8 warps: S-phase 2(n)x4(m) warp tiles 32x16; PV-phase 2(n)x4(d) tiles 32x16.
// Smem (words): QH/QL [64][72], KP H/L (K then P) [64][72], VH/VL [64][72],
//               rmax[64], rsum[64], rscale[64], red[4][64].
// ---------------------------------------------------------------------------
#define OFF_QH  0
#define OFF_QL  (64 * AT_STRIDE)
#define OFF_KPH (2 * 64 * AT_STRIDE)
#define OFF_KPL (3 * 64 * AT_STRIDE)
#define OFF_VH  (4 * 64 * AT_STRIDE)
#define OFF_VL  (5 * 64 * AT_STRIDE)
#define OFF_RMAX (6 * 64 * AT_STRIDE)
#define OFF_RSUM (OFF_RMAX + 64)
#define OFF_RSCL (OFF_RSUM + 64)
#define OFF_RED  (OFF_RSCL + 64)
#define ATTN_SMEM_WORDS (OFF_RED + 256)

__global__ void __launch_bounds__(256, 2)
attn_fused(const float* __restrict__ mask)
{
    extern __shared__ uint32_t dsm[];
    uint32_t* QH  = dsm + OFF_QH;
    uint32_t* QL  = dsm + OFF_QL;
    uint32_t* KPH = dsm + OFF_KPH;
    uint32_t* KPL = dsm + OFF_KPL;
    uint32_t* VH  = dsm + OFF_VH;
    uint32_t* VL  = dsm + OFF_VL;
    float* RMAX = (float*)(dsm + OFF_RMAX);
    float* RSUM = (float*)(dsm + OFF_RSUM);
    float* RSCL = (float*)(dsm + OFF_RSCL);
    float* RED  = (float*)(dsm + OFF_RED);

    const int tid  = threadIdx.x;
    const int w    = tid >> 5;
    const int lane = tid & 31;
    const int g    = lane >> 2;
    const int tg   = lane & 3;
    const int wn   = w >> 2;   // n-split (0..1), both phases
    const int wx   = w & 3;    // m-split (S) / d-split (PV)

    const int n0 = blockIdx.x * 64;
    const int bh = blockIdx.z;
    const int b = bh >> 2, h = bh & 3;

    const float* qg = g_q + (size_t)b * Dd * Nn;
    const float* kg = g_k + (size_t)b * Dd * Mm;
    const float* vg = g_v + (size_t)b * Dd * Mm;

    // loader mapping: 64 rows (d), 4 chunks of 16 cols
    const int ld_d = tid >> 2;
    const int ld_c = (tid & 3) * 16;

    // --- load Q tile once: QH/QL[d][n] ---
    {
        const float* qp = qg + (size_t)(ld_d * Hh + h) * Nn + n0 + ld_c;
        #pragma unroll
        for (int i = 0; i < 4; i++) {
            float4 v4 = *(const float4*)(qp + i * 4);
            int c = ld_c + i * 4;
            uint32_t hh, ll;
            split_tf32(v4.x, hh, ll); QH[ld_d*AT_STRIDE + c+0]=hh; QL[ld_d*AT_STRIDE + c+0]=ll;
            split_tf32(v4.y, hh, ll); QH[ld_d*AT_STRIDE + c+1]=hh; QL[ld_d*AT_STRIDE + c+1]=ll;
            split_tf32(v4.z, hh, ll); QH[ld_d*AT_STRIDE + c+2]=hh; QL[ld_d*AT_STRIDE + c+2]=ll;
            split_tf32(v4.w, hh, ll); QH[ld_d*AT_STRIDE + c+3]=hh; QL[ld_d*AT_STRIDE + c+3]=ll;
        }
    }
    if (tid < 64) { RMAX[tid] = -FLT_MAX; RSUM[tid] = 0.f; }

    float o[2][2][4] = {};   // O accumulator: rows n, cols d

    const int rl0_base = wn * 32;     // local row base for this warp

    for (int mi = 0; mi < Mm / 64; mi++) {
        const int m0 = mi * 64;
        __syncthreads();   // protect KP (P reads) and V (mma reads) from reload

        // --- load K tile: KPH/KPL[d(k)][m]; V tile transposed: VH/VL[m(k)][d] ---
        {
            const float* kp = kg + (size_t)(ld_d * Hh + h) * Mm + m0 + ld_c;
            const float* vp = vg + (size_t)(ld_d * Hh + h) * Mm + m0 + ld_c;
            #pragma unroll
            for (int i = 0; i < 4; i++) {
                float4 kv = *(const float4*)(kp + i * 4);
                float4 vv = *(const float4*)(vp + i * 4);
                int c = ld_c + i * 4;
                uint32_t hh, ll;
                split_tf32(kv.x, hh, ll); KPH[ld_d*AT_STRIDE + c+0]=hh; KPL[ld_d*AT_STRIDE + c+0]=ll;
                split_tf32(kv.y, hh, ll); KPH[ld_d*AT_STRIDE + c+1]=hh; KPL[ld_d*AT_STRIDE + c+1]=ll;
                split_tf32(kv.z, hh, ll); KPH[ld_d*AT_STRIDE + c+2]=hh; KPL[ld_d*AT_STRIDE + c+2]=ll;
                split_tf32(kv.w, hh, ll); KPH[ld_d*AT_STRIDE + c+3]=hh; KPL[ld_d*AT_STRIDE + c+3]=ll;
                split_tf32(vv.x, hh, ll); VH[(c+0)*AT_STRIDE + ld_d]=hh; VL[(c+0)*AT_STRIDE + ld_d]=ll;
                split_tf32(vv.y, hh, ll); VH[(c+1)*AT_STRIDE + ld_d]=hh; VL[(c+1)*AT_STRIDE + ld_d]=ll;
                split_tf32(vv.z, hh, ll); VH[(c+2)*AT_STRIDE + ld_d]=hh; VL[(c+2)*AT_STRIDE + ld_d]=ll;
                split_tf32(vv.w, hh, ll); VH[(c+3)*AT_STRIDE + ld_d]=hh; VL[(c+3)*AT_STRIDE + ld_d]=ll;
            }
        }
        __syncthreads();

        // --- S = Q^T K  (warp tile: 32 n x 16 m) ---
        float s[2][2][4] = {};
        #pragma unroll
        for (int ks = 0; ks < 8; ks++) {
            const int kb = ks * 8;
            uint32_t ah[2][4], al[2][4], bh2[2][2], bl2[2][2];
            #pragma unroll
            for (int mt = 0; mt < 2; mt++) {
                int n = rl0_base + mt * 16;
                ah[mt][0]=QH[(kb+tg  )*AT_STRIDE + n+g  ]; al[mt][0]=QL[(kb+tg  )*AT_STRIDE + n+g  ];
                ah[mt][1]=QH[(kb+tg  )*AT_STRIDE + n+g+8]; al[mt][1]=QL[(kb+tg  )*AT_STRIDE + n+g+8];
                ah[mt][2]=QH[(kb+tg+4)*AT_STRIDE + n+g  ]; al[mt][2]=QL[(kb+tg+4)*AT_STRIDE + n+g  ];
                ah[mt][3]=QH[(kb+tg+4)*AT_STRIDE + n+g+8]; al[mt][3]=QL[(kb+tg+4)*AT_STRIDE + n+g+8];
            }
            #pragma unroll
            for (int nt = 0; nt < 2; nt++) {
                int m = wx * 16 + nt * 8 + g;
                bh2[nt][0]=KPH[(kb+tg  )*AT_STRIDE + m]; bl2[nt][0]=KPL[(kb+tg  )*AT_STRIDE + m];
                bh2[nt][1]=KPH[(kb+tg+4)*AT_STRIDE + m]; bl2[nt][1]=KPL[(kb+tg+4)*AT_STRIDE + m];
            }
            #pragma unroll
            for (int mt = 0; mt < 2; mt++)
                #pragma unroll
                for (int nt = 0; nt < 2; nt++)
                    mma3(s[mt][nt], ah[mt], al[mt], bh2[nt], bl2[nt]);
        }

        // --- mask + scale + per-row tile max ---
        float pmax[2][2];
        pmax[0][0]=pmax[0][1]=pmax[1][0]=pmax[1][1] = -FLT_MAX;
        #pragma unroll
        for (int mt = 0; mt < 2; mt++) {
            int gn0 = n0 + rl0_base + mt * 16 + g;
            #pragma unroll
            for (int nt = 0; nt < 2; nt++) {
                int gm = m0 + wx * 16 + nt * 8 + 2 * tg;
                float2 mk0 = *(const float2*)&mask[((size_t)b * Nn + gn0    ) * Mm + gm];
                float2 mk1 = *(const float2*)&mask[((size_t)b * Nn + gn0 + 8) * Mm + gm];
                s[mt][nt][0] = (mk0.x > 0.f) ? s[mt][nt][0] * 0.125f : -FLT_MAX;
                s[mt][nt][1] = (mk0.y > 0.f) ? s[mt][nt][1] * 0.125f : -FLT_MAX;
                s[mt][nt][2] = (mk1.x > 0.f) ? s[mt][nt][2] * 0.125f : -FLT_MAX;
                s[mt][nt][3] = (mk1.y > 0.f) ? s[mt][nt][3] * 0.125f : -FLT_MAX;
                pmax[mt][0] = fmaxf(pmax[mt][0], fmaxf(s[mt][nt][0], s[mt][nt][1]));
                pmax[mt][1] = fmaxf(pmax[mt][1], fmaxf(s[mt][nt][2], s[mt][nt][3]));
            }
        }
        #pragma unroll
        for (int mt = 0; mt < 2; mt++)
            #pragma unroll
            for (int r = 0; r < 2; r++) {
                pmax[mt][r] = fmaxf(pmax[mt][r], __shfl_xor_sync(0xffffffffu, pmax[mt][r], 1));
                pmax[mt][r] = fmaxf(pmax[mt][r], __shfl_xor_sync(0xffffffffu, pmax[mt][r], 2));
            }
        if (tg == 0) {
            #pragma unroll
            for (int mt = 0; mt < 2; mt++) {
                RED[wx * 64 + rl0_base + mt * 16 + g    ] = pmax[mt][0];
                RED[wx * 64 + rl0_base + mt * 16 + g + 8] = pmax[mt][1];
            }
        }
        __syncthreads();
        if (tid < 64) {
            float tm = fmaxf(fmaxf(RED[tid], RED[64 + tid]),
                             fmaxf(RED[128 + tid], RED[192 + tid]));
            float om = RMAX[tid];
            float nm = fmaxf(om, tm);
            float sc = __expf(om - nm);
            RMAX[tid] = nm;
            RSCL[tid] = sc;
            RSUM[tid] *= sc;
        }
        __syncthreads();

        // --- exp, write P (overwrites K buffer), partial row sums ---
        float psum[2][2] = {};
        #pragma unroll
        for (int mt = 0; mt < 2; mt++) {
            int rl0 = rl0_base + mt * 16 + g;
            float mx0 = RMAX[rl0], mx1 = RMAX[rl0 + 8];
            #pragma unroll
            for (int nt = 0; nt < 2; nt++) {
                int mc = wx * 16 + nt * 8 + 2 * tg;
                float p0 = __expf(s[mt][nt][0] - mx0);
                float p1 = __expf(s[mt][nt][1] - mx0);
                float p2 = __expf(s[mt][nt][2] - mx1);
                float p3 = __expf(s[mt][nt][3] - mx1);
                uint32_t hh, ll;
                split_tf32(p0, hh, ll); KPH[(mc  )*AT_STRIDE + rl0    ]=hh; KPL[(mc  )*AT_STRIDE + rl0    ]=ll;
                split_tf32(p1, hh, ll); KPH[(mc+1)*AT_STRIDE + rl0    ]=hh; KPL[(mc+1)*AT_STRIDE + rl0    ]=ll;
                split_tf32(p2, hh, ll); KPH[(mc  )*AT_STRIDE + rl0 + 8]=hh; KPL[(mc  )*AT_STRIDE + rl0 + 8]=ll;
                split_tf32(p3, hh, ll); KPH[(mc+1)*AT_STRIDE + rl0 + 8]=hh; KPL[(mc+1)*AT_STRIDE + rl0 + 8]=ll;
                psum[mt][0] += p0 + p1;
                psum[mt][1] += p2 + p3;
            }
        }
        #pragma unroll
        for (int mt = 0; mt < 2; mt++)
            #pragma unroll
            for (int r = 0; r < 2; r++) {
                psum[mt][r] += __shfl_xor_sync(0xffffffffu, psum[mt][r], 1);
                psum[mt][r] += __shfl_xor_sync(0xffffffffu, psum[mt][r], 2);
            }
        if (tg == 0) {
            #pragma unroll
            for (int mt = 0; mt < 2; mt++) {
                RED[wx * 64 + rl0_base + mt * 16 + g    ] = psum[mt][0];
                RED[wx * 64 + rl0_base + mt * 16 + g + 8] = psum[mt][1];
            }
        }
        __syncthreads();
        if (tid < 64)
            RSUM[tid] += RED[tid] + RED[64 + tid] + RED[128 + tid] + RED[192 + tid];

        // --- PV: O = O*scale + P·V  (warp tile: 32 n x 16 d) ---
        #pragma unroll
        for (int mt = 0; mt < 2; mt++) {
            int rl0 = rl0_base + mt * 16 + g;
            float sc0 = RSCL[rl0], sc1 = RSCL[rl0 + 8];
            #pragma unroll
            for (int nt = 0; nt < 2; nt++) {
                o[mt][nt][0] *= sc0; o[mt][nt][1] *= sc0;
                o[mt][nt][2] *= sc1; o[mt][nt][3] *= sc1;
            }
        }
        #pragma unroll
        for (int ks = 0; ks < 8; ks++) {
            const int kb = ks * 8;
            uint32_t ah[2][4], al[2][4], bh2[2][2], bl2[2][2];
            #pragma unroll
            for (int mt = 0; mt < 2; mt++) {
                int n = rl0_base + mt * 16;
                ah[mt][0]=KPH[(kb+tg  )*AT_STRIDE + n+g  ]; al[mt][0]=KPL[(kb+tg  )*AT_STRIDE + n+g  ];
                ah[mt][1]=KPH[(kb+tg  )*AT_STRIDE + n+g+8]; al[mt][1]=KPL[(kb+tg  )*AT_STRIDE + n+g+8];
                ah[mt][2]=KPH[(kb+tg+4)*AT_STRIDE + n+g  ]; al[mt][2]=KPL[(kb+tg+4)*AT_STRIDE + n+g  ];
                ah[mt][3]=KPH[(kb+tg+4)*AT_STRIDE + n+g+8]; al[mt][3]=KPL[(kb+tg+4)*AT_STRIDE + n+g+8];
            }
            #pragma unroll
            for (int nt = 0; nt < 2; nt++) {
                int d = wx * 16 + nt * 8 + g;
                bh2[nt][0]=VH[(kb+tg  )*AT_STRIDE + d]; bl2[nt][0]=VL[(kb+tg  )*AT_STRIDE + d];
                bh2[nt][1]=VH[(kb+tg+4)*AT_STRIDE + d]; bl2[nt][1]=VL[(kb+tg+4)*AT_STRIDE + d];
            }
            #pragma unroll
            for (int mt = 0; mt < 2; mt++)
                #pragma unroll
                for (int nt = 0; nt < 2; nt++)
                    mma3(o[mt][nt], ah[mt], al[mt], bh2[nt], bl2[nt]);
        }
    }

    __syncthreads();
    // --- epilogue: normalize and write msg[b, d*4+h, n] ---
    float* mp = g_msg + (size_t)b * Dd * Nn;
    #pragma unroll
    for (int mt = 0; mt < 2; mt++) {
        int rl0 = rl0_base + mt * 16 + g;
        float inv0 = 1.f / RSUM[rl0];
        float inv1 = 1.f / RSUM[rl0 + 8];
        int gn0 = n0 + rl0, gn1 = gn0 + 8;
        #pragma unroll
        for (int nt = 0; nt < 2; nt++) {
            int d = wx * 16 + nt * 8 + 2 * tg;
            mp[(size_t)(d       * Hh + h) * Nn + gn0] = o[mt][nt][0] * inv0;
            mp[(size_t)((d + 1) * Hh + h) * Nn + gn0] = o[mt][nt][1] * inv0;
            mp[(size_t)(d       * Hh + h) * Nn + gn1] = o[mt][nt][2] * inv1;
            mp[(size_t)((d + 1) * Hh + h) * Nn + gn1] = o[mt][nt][3] * inv1;
        }
    }
}

// ---------------------------------------------------------------------------
extern "C" void kernel_launch(void* const* d_in, const int* in_sizes, int n_in,
                              void* d_out, int out_size)
{
    const float* x      = (const float*)d_in[0];
    const float* source = (const float*)d_in[1];
    const float* mask   = (const float*)d_in[2];
    const float* Wq = (const float*)d_in[3];
    const float* bq = (const float*)d_in[4];
    const float* Wk = (const float*)d_in[5];
    const float* bk = (const float*)d_in[6];
    const float* Wv = (const float*)d_in[7];
    const float* bv = (const float*)d_in[8];
    const float* Wm = (const float*)d_in[9];
    const float* bm = (const float*)d_in[10];
    const float* W1 = (const float*)d_in[11];
    const float* b1 = (const float*)d_in[12];
    const float* gamma = (const float*)d_in[13];
    const float* beta  = (const float*)d_in[14];
    const float* rmean = (const float*)d_in[15];
    const float* rvar  = (const float*)d_in[16];
    const float* W2 = (const float*)d_in[17];
    const float* b2 = (const float*)d_in[18];
    float* out = (float*)d_out;

    float *qb, *kb, *vb, *msgb, *messageb, *hb;
    cudaGetSymbolAddress((void**)&qb, g_q);
    cudaGetSymbolAddress((void**)&kb, g_k);
    cudaGetSymbolAddress((void**)&vb, g_v);
    cudaGetSymbolAddress((void**)&msgb, g_msg);
    cudaGetSymbolAddress((void**)&messageb, g_message);
    cudaGetSymbolAddress((void**)&hb, g_h);

    const int SMEM_GEMM = 4 * 32 * SM_STRIDE * 4;
    const int SMEM_ATTN = ATTN_SMEM_WORDS * 4;

    cudaFuncSetAttribute(gemm_mma<256, 256, false, false>,
                         cudaFuncAttributeMaxDynamicSharedMemorySize, SMEM_GEMM);
    cudaFuncSetAttribute(gemm_mma<512, 512, true, true>,
                         cudaFuncAttributeMaxDynamicSharedMemorySize, SMEM_GEMM);
    cudaFuncSetAttribute(gemm_mma<256, 512, false, false>,
                         cudaFuncAttributeMaxDynamicSharedMemorySize, SMEM_GEMM);
    cudaFuncSetAttribute(attn_fused,
                         cudaFuncAttributeMaxDynamicSharedMemorySize, SMEM_ATTN);

    // q, k, v projections
    gemm_mma<256, 256, false, false><<<dim3(16, 2, 4), 256, SMEM_GEMM>>>(
        Wq, bq, x, nullptr, qb, nullptr, nullptr, nullptr, nullptr);
    gemm_mma<256, 256, false, false><<<dim3(16, 2, 4), 256, SMEM_GEMM>>>(
        Wk, bk, source, nullptr, kb, nullptr, nullptr, nullptr, nullptr);
    gemm_mma<256, 256, false, false><<<dim3(16, 2, 4), 256, SMEM_GEMM>>>(
        Wv, bv, source, nullptr, vb, nullptr, nullptr, nullptr, nullptr);

    // fused attention (scores + mask + softmax + PV)
    attn_fused<<<dim3(32, 1, 16), 256, SMEM_ATTN>>>(mask);

    // message projection
    gemm_mma<256, 256, false, false><<<dim3(16, 2, 4), 256, SMEM_GEMM>>>(
        Wm, bm, msgb, nullptr, messageb, nullptr, nullptr, nullptr, nullptr);

    // MLP layer 1 (concat[x, message]) + BN + ReLU
    gemm_mma<512, 512, true, true><<<dim3(16, 4, 4), 256, SMEM_GEMM>>>(
        W1, b1, x, messageb, hb, gamma, beta, rmean, rvar);

    // MLP layer 2 -> output
    gemm_mma<256, 512, false, false><<<dim3(16, 2, 4), 256, SMEM_GEMM>>>(
        W2, b2, hb, nullptr, out, nullptr, nullptr, nullptr, nullptr);
}

// round 7
// speedup vs baseline: 1.0007x; 1.0007x over previous
#include <cuda_runtime.h>
#include <math.h>
#include <float.h>
#include <stdint.h>

// Problem constants
#define Bn   4
#define Dd   256
#define Nn   2048
#define Mm   2048
#define Hh   4
#define DIMh 64

// Scratch (allocation-free: __device__ globals)
__device__ float g_q[Bn * Dd * Nn];
__device__ float g_k[Bn * Dd * Mm];
__device__ float g_v[Bn * Dd * Mm];
__device__ float g_msg[Bn * Dd * Nn];
__device__ float g_message[Bn * Dd * Nn];
__device__ float g_h[Bn * 2 * Dd * Nn];

// ---------------------------------------------------------------------------
// tf32 helpers
// ---------------------------------------------------------------------------
__device__ __forceinline__ uint32_t f2tf(float x)
{
    uint32_t r;
    asm("cvt.rna.tf32.f32 %0, %1;" : "=r"(r) : "f"(x));
    return r;
}
__device__ __forceinline__ void split_tf32(float x, uint32_t& hi, uint32_t& lo)
{
    hi = f2tf(x);
    lo = f2tf(x - __uint_as_float(hi));
}

__device__ __forceinline__ void mma_tf32(float (&d)[4],
                                         uint32_t a0, uint32_t a1, uint32_t a2, uint32_t a3,
                                         uint32_t b0, uint32_t b1)
{
    asm volatile(
        "mma.sync.aligned.m16n8k8.row.col.f32.tf32.tf32.f32 "
        "{%0,%1,%2,%3}, {%4,%5,%6,%7}, {%8,%9}, {%0,%1,%2,%3};\n"
        : "+f"(d[0]), "+f"(d[1]), "+f"(d[2]), "+f"(d[3])
        : "r"(a0), "r"(a1), "r"(a2), "r"(a3), "r"(b0), "r"(b1));
}

__device__ __forceinline__ void mma3(float (&d)[4],
                                     const uint32_t (&ah)[4], const uint32_t (&al)[4],
                                     const uint32_t (&bh)[2], const uint32_t (&bl)[2])
{
    mma_tf32(d, al[0], al[1], al[2], al[3], bh[0], bh[1]);
    mma_tf32(d, ah[0], ah[1], ah[2], ah[3], bl[0], bl[1]);
    mma_tf32(d, ah[0], ah[1], ah[2], ah[3], bh[0], bh[1]);
}

#define SM_STRIDE 136   // gemm tiles: 128 cols + 8 pad (conflict-free fragments)
#define AT_STRIDE 72    // attention tiles: 64 cols + 8 pad

// ---------------------------------------------------------------------------
// Generic per-batch 1x1-conv GEMM via 3xTF32 mma (unchanged from R5):
//   Y[b,o,n] = sum_c W[o,c] * X[b,c,n] + bias[o]
// ---------------------------------------------------------------------------
template<int OUTC, int INC, bool CONCAT, bool BNRELU>
__global__ void __launch_bounds__(256)
gemm_mma(const float* __restrict__ W, const float* __restrict__ bias,
         const float* __restrict__ X0, const float* __restrict__ X1,
         float* __restrict__ Y,
         const float* __restrict__ gamma, const float* __restrict__ beta,
         const float* __restrict__ rmean, const float* __restrict__ rvar)
{
    extern __shared__ uint32_t dsm[];
    uint32_t (*AsH)[SM_STRIDE] = (uint32_t(*)[SM_STRIDE])(dsm);
    uint32_t (*AsL)[SM_STRIDE] = (uint32_t(*)[SM_STRIDE])(dsm + 32 * SM_STRIDE);
    uint32_t (*BsH)[SM_STRIDE] = (uint32_t(*)[SM_STRIDE])(dsm + 64 * SM_STRIDE);
    uint32_t (*BsL)[SM_STRIDE] = (uint32_t(*)[SM_STRIDE])(dsm + 96 * SM_STRIDE);

    const int tid = threadIdx.x;
    const int n0 = blockIdx.x * 128;
    const int o0 = blockIdx.y * 128;
    const int b  = blockIdx.z;
    const int XC = CONCAT ? (INC / 2) : INC;
    const float* x0 = X0 + (size_t)b * XC * Nn;
    const float* x1 = CONCAT ? (X1 + (size_t)b * XC * Nn) : nullptr;

    const int w      = tid >> 5;
    const int lane   = tid & 31;
    const int g      = lane >> 2;
    const int tg     = lane & 3;
    const int warp_m = w >> 2;
    const int warp_n = w & 3;

    float acc[4][4][4] = {};

    const int a_row  = tid >> 1;
    const int a_half = tid & 1;
    const int b_row  = tid >> 3;
    const int b_col  = (tid & 7) * 16;

    for (int c0 = 0; c0 < INC; c0 += 32) {
        {
            const float* wp = W + (size_t)(o0 + a_row) * INC + c0 + a_half * 16;
            #pragma unroll
            for (int q = 0; q < 4; q++) {
                float4 v4 = *(const float4*)(wp + q * 4);
                int cl = a_half * 16 + q * 4;
                uint32_t h0,l0,h1,l1,h2,l2,h3,l3;
                split_tf32(v4.x, h0, l0); split_tf32(v4.y, h1, l1);
                split_tf32(v4.z, h2, l2); split_tf32(v4.w, h3, l3);
                AsH[cl+0][a_row]=h0; AsL[cl+0][a_row]=l0;
                AsH[cl+1][a_row]=h1; AsL[cl+1][a_row]=l1;
                AsH[cl+2][a_row]=h2; AsL[cl+2][a_row]=l2;
                AsH[cl+3][a_row]=h3; AsL[cl+3][a_row]=l3;
            }
        }
        {
            int c = c0 + b_row;
            const float* xp;
            if (!CONCAT || c < INC / 2) xp = x0 + (size_t)c * Nn + n0 + b_col;
            else                        xp = x1 + (size_t)(c - INC / 2) * Nn + n0 + b_col;
            #pragma unroll
            for (int q = 0; q < 4; q++) {
                float4 v4 = *(const float4*)(xp + q * 4);
                int cc = b_col + q * 4;
                uint32_t h,l;
                split_tf32(v4.x, h, l); BsH[b_row][cc+0]=h; BsL[b_row][cc+0]=l;
                split_tf32(v4.y, h, l); BsH[b_row][cc+1]=h; BsL[b_row][cc+1]=l;
                split_tf32(v4.z, h, l); BsH[b_row][cc+2]=h; BsL[b_row][cc+2]=l;
                split_tf32(v4.w, h, l); BsH[b_row][cc+3]=h; BsL[b_row][cc+3]=l;
            }
        }
        __syncthreads();

        #pragma unroll
        for (int ks = 0; ks < 4; ks++) {
            const int kb = ks * 8;
            uint32_t ah[4][4], al[4][4], bh[4][2], bl[4][2];
            #pragma unroll
            for (int mt = 0; mt < 4; mt++) {
                int m = warp_m * 64 + mt * 16;
                ah[mt][0]=AsH[kb+tg  ][m+g  ]; al[mt][0]=AsL[kb+tg  ][m+g  ];
                ah[mt][1]=AsH[kb+tg  ][m+g+8]; al[mt][1]=AsL[kb+tg  ][m+g+8];
                ah[mt][2]=AsH[kb+tg+4][m+g  ]; al[mt][2]=AsL[kb+tg+4][m+g  ];
                ah[mt][3]=AsH[kb+tg+4][m+g+8]; al[mt][3]=AsL[kb+tg+4][m+g+8];
            }
            #pragma unroll
            for (int nt = 0; nt < 4; nt++) {
                int n = warp_n * 32 + nt * 8 + g;
                bh[nt][0]=BsH[kb+tg  ][n]; bl[nt][0]=BsL[kb+tg  ][n];
                bh[nt][1]=BsH[kb+tg+4][n]; bl[nt][1]=BsL[kb+tg+4][n];
            }
            #pragma unroll
            for (int mt = 0; mt < 4; mt++)
                #pragma unroll
                for (int nt = 0; nt < 4; nt++)
                    mma3(acc[mt][nt], ah[mt], al[mt], bh[nt], bl[nt]);
        }
        __syncthreads();
    }

    float* yb = Y + (size_t)b * OUTC * Nn;
    #pragma unroll
    for (int mt = 0; mt < 4; mt++) {
        int r0 = o0 + warp_m * 64 + mt * 16 + g;
        int r1 = r0 + 8;
        float bv0 = bias[r0], bv1 = bias[r1];
        float sc0 = 1.f, sh0 = 0.f, sc1 = 1.f, sh1 = 0.f;
        if (BNRELU) {
            float rs0 = rsqrtf(rvar[r0] + 1e-3f);
            sc0 = gamma[r0] * rs0; sh0 = beta[r0] - rmean[r0] * sc0;
            float rs1 = rsqrtf(rvar[r1] + 1e-3f);
            sc1 = gamma[r1] * rs1; sh1 = beta[r1] - rmean[r1] * sc1;
        }
        #pragma unroll
        for (int nt = 0; nt < 4; nt++) {
            int n = n0 + warp_n * 32 + nt * 8 + 2 * tg;
            float t0 = acc[mt][nt][0] + bv0;
            float t1 = acc[mt][nt][1] + bv0;
            float t2 = acc[mt][nt][2] + bv1;
            float t3 = acc[mt][nt][3] + bv1;
            if (BNRELU) {
                t0 = fmaxf(t0 * sc0 + sh0, 0.f);
                t1 = fmaxf(t1 * sc0 + sh0, 0.f);
                t2 = fmaxf(t2 * sc1 + sh1, 0.f);
                t3 = fmaxf(t3 * sc1 + sh1, 0.f);
            }
            *(float2*)&yb[(size_t)r0 * Nn + n] = make_float2(t0, t1);
            *(float2*)&yb[(size_t)r1 * Nn + n] = make_float2(t2, t3);
        }
    }
}

// ---------------------------------------------------------------------------
// Fused flash attention (3xTF32):
//   per (b,h): msg[:, n] = softmax_m( mask ? q·k/8 : -inf ) · v
// Block: 64 queries (n), head-dim 64 resident; m streamed in tiles of 64.
// 8 warps: S-phase 2(n)x4(m) warp tiles 32x16; PV-phase 2(n)x4(d) tiles 32x16.
// Smem (words): QH/QL [64][72], KP H/L (K then P) [64][72], VH/VL [64][72],
//               rmax[64], rsum[64], rscale[64], red[4][64].
// ---------------------------------------------------------------------------
#define OFF_QH  0
#define OFF_QL  (64 * AT_STRIDE)
#define OFF_KPH (2 * 64 * AT_STRIDE)
#define OFF_KPL (3 * 64 * AT_STRIDE)
#define OFF_VH  (4 * 64 * AT_STRIDE)
#define OFF_VL  (5 * 64 * AT_STRIDE)
#define OFF_RMAX (6 * 64 * AT_STRIDE)
#define OFF_RSUM (OFF_RMAX + 64)
#define OFF_RSCL (OFF_RSUM + 64)
#define OFF_RED  (OFF_RSCL + 64)
#define ATTN_SMEM_WORDS (OFF_RED + 256)

__global__ void __launch_bounds__(256, 2)
attn_fused(const float* __restrict__ mask)
{
    extern __shared__ uint32_t dsm[];
    uint32_t* QH  = dsm + OFF_QH;
    uint32_t* QL  = dsm + OFF_QL;
    uint32_t* KPH = dsm + OFF_KPH;
    uint32_t* KPL = dsm + OFF_KPL;
    uint32_t* VH  = dsm + OFF_VH;
    uint32_t* VL  = dsm + OFF_VL;
    float* RMAX = (float*)(dsm + OFF_RMAX);
    float* RSUM = (float*)(dsm + OFF_RSUM);
    float* RSCL = (float*)(dsm + OFF_RSCL);
    float* RED  = (float*)(dsm + OFF_RED);

    const int tid  = threadIdx.x;
    const int w    = tid >> 5;
    const int lane = tid & 31;
    const int g    = lane >> 2;
    const int tg   = lane & 3;
    const int wn   = w >> 2;   // n-split (0..1), both phases
    const int wx   = w & 3;    // m-split (S) / d-split (PV)

    const int n0 = blockIdx.x * 64;
    const int bh = blockIdx.z;
    const int b = bh >> 2, h = bh & 3;

    const float* qg = g_q + (size_t)b * Dd * Nn;
    const float* kg = g_k + (size_t)b * Dd * Mm;
    const float* vg = g_v + (size_t)b * Dd * Mm;

    // loader mapping: 64 rows (d), 4 chunks of 16 cols
    const int ld_d = tid >> 2;
    const int ld_c = (tid & 3) * 16;

    // --- load Q tile once: QH/QL[d][n] ---
    {
        const float* qp = qg + (size_t)(ld_d * Hh + h) * Nn + n0 + ld_c;
        #pragma unroll
        for (int i = 0; i < 4; i++) {
            float4 v4 = *(const float4*)(qp + i * 4);
            int c = ld_c + i * 4;
            uint32_t hh, ll;
            split_tf32(v4.x, hh, ll); QH[ld_d*AT_STRIDE + c+0]=hh; QL[ld_d*AT_STRIDE + c+0]=ll;
            split_tf32(v4.y, hh, ll); QH[ld_d*AT_STRIDE + c+1]=hh; QL[ld_d*AT_STRIDE + c+1]=ll;
            split_tf32(v4.z, hh, ll); QH[ld_d*AT_STRIDE + c+2]=hh; QL[ld_d*AT_STRIDE + c+2]=ll;
            split_tf32(v4.w, hh, ll); QH[ld_d*AT_STRIDE + c+3]=hh; QL[ld_d*AT_STRIDE + c+3]=ll;
        }
    }
    if (tid < 64) { RMAX[tid] = -FLT_MAX; RSUM[tid] = 0.f; }

    float o[2][2][4] = {};   // O accumulator: rows n, cols d

    const int rl0_base = wn * 32;     // local row base for this warp

    for (int mi = 0; mi < Mm / 64; mi++) {
        const int m0 = mi * 64;
        __syncthreads();   // protect KP (P reads) and V (mma reads) from reload

        // --- load K tile: KPH/KPL[d(k)][m]; V tile transposed: VH/VL[m(k)][d] ---
        {
            const float* kp = kg + (size_t)(ld_d * Hh + h) * Mm + m0 + ld_c;
            const float* vp = vg + (size_t)(ld_d * Hh + h) * Mm + m0 + ld_c;
            #pragma unroll
            for (int i = 0; i < 4; i++) {
                float4 kv = *(const float4*)(kp + i * 4);
                float4 vv = *(const float4*)(vp + i * 4);
                int c = ld_c + i * 4;
                uint32_t hh, ll;
                split_tf32(kv.x, hh, ll); KPH[ld_d*AT_STRIDE + c+0]=hh; KPL[ld_d*AT_STRIDE + c+0]=ll;
                split_tf32(kv.y, hh, ll); KPH[ld_d*AT_STRIDE + c+1]=hh; KPL[ld_d*AT_STRIDE + c+1]=ll;
                split_tf32(kv.z, hh, ll); KPH[ld_d*AT_STRIDE + c+2]=hh; KPL[ld_d*AT_STRIDE + c+2]=ll;
                split_tf32(kv.w, hh, ll); KPH[ld_d*AT_STRIDE + c+3]=hh; KPL[ld_d*AT_STRIDE + c+3]=ll;
                split_tf32(vv.x, hh, ll); VH[(c+0)*AT_STRIDE + ld_d]=hh; VL[(c+0)*AT_STRIDE + ld_d]=ll;
                split_tf32(vv.y, hh, ll); VH[(c+1)*AT_STRIDE + ld_d]=hh; VL[(c+1)*AT_STRIDE + ld_d]=ll;
                split_tf32(vv.z, hh, ll); VH[(c+2)*AT_STRIDE + ld_d]=hh; VL[(c+2)*AT_STRIDE + ld_d]=ll;
                split_tf32(vv.w, hh, ll); VH[(c+3)*AT_STRIDE + ld_d]=hh; VL[(c+3)*AT_STRIDE + ld_d]=ll;
            }
        }
        __syncthreads();

        // --- S = Q^T K  (warp tile: 32 n x 16 m) ---
        float s[2][2][4] = {};
        #pragma unroll
        for (int ks = 0; ks < 8; ks++) {
            const int kb = ks * 8;
            uint32_t ah[2][4], al[2][4], bh2[2][2], bl2[2][2];
            #pragma unroll
            for (int mt = 0; mt < 2; mt++) {
                int n = rl0_base + mt * 16;
                ah[mt][0]=QH[(kb+tg  )*AT_STRIDE + n+g  ]; al[mt][0]=QL[(kb+tg  )*AT_STRIDE + n+g  ];
                ah[mt][1]=QH[(kb+tg  )*AT_STRIDE + n+g+8]; al[mt][1]=QL[(kb+tg  )*AT_STRIDE + n+g+8];
                ah[mt][2]=QH[(kb+tg+4)*AT_STRIDE + n+g  ]; al[mt][2]=QL[(kb+tg+4)*AT_STRIDE + n+g  ];
                ah[mt][3]=QH[(kb+tg+4)*AT_STRIDE + n+g+8]; al[mt][3]=QL[(kb+tg+4)*AT_STRIDE + n+g+8];
            }
            #pragma unroll
            for (int nt = 0; nt < 2; nt++) {
                int m = wx * 16 + nt * 8 + g;
                bh2[nt][0]=KPH[(kb+tg  )*AT_STRIDE + m]; bl2[nt][0]=KPL[(kb+tg  )*AT_STRIDE + m];
                bh2[nt][1]=KPH[(kb+tg+4)*AT_STRIDE + m]; bl2[nt][1]=KPL[(kb+tg+4)*AT_STRIDE + m];
            }
            #pragma unroll
            for (int mt = 0; mt < 2; mt++)
                #pragma unroll
                for (int nt = 0; nt < 2; nt++)
                    mma3(s[mt][nt], ah[mt], al[mt], bh2[nt], bl2[nt]);
        }

        // --- mask + scale + per-row tile max ---
        float pmax[2][2];
        pmax[0][0]=pmax[0][1]=pmax[1][0]=pmax[1][1] = -FLT_MAX;
        #pragma unroll
        for (int mt = 0; mt < 2; mt++) {
            int gn0 = n0 + rl0_base + mt * 16 + g;
            #pragma unroll
            for (int nt = 0; nt < 2; nt++) {
                int gm = m0 + wx * 16 + nt * 8 + 2 * tg;
                float2 mk0 = *(const float2*)&mask[((size_t)b * Nn + gn0    ) * Mm + gm];
                float2 mk1 = *(const float2*)&mask[((size_t)b * Nn + gn0 + 8) * Mm + gm];
                s[mt][nt][0] = (mk0.x > 0.f) ? s[mt][nt][0] * 0.125f : -FLT_MAX;
                s[mt][nt][1] = (mk0.y > 0.f) ? s[mt][nt][1] * 0.125f : -FLT_MAX;
                s[mt][nt][2] = (mk1.x > 0.f) ? s[mt][nt][2] * 0.125f : -FLT_MAX;
                s[mt][nt][3] = (mk1.y > 0.f) ? s[mt][nt][3] * 0.125f : -FLT_MAX;
                pmax[mt][0] = fmaxf(pmax[mt][0], fmaxf(s[mt][nt][0], s[mt][nt][1]));
                pmax[mt][1] = fmaxf(pmax[mt][1], fmaxf(s[mt][nt][2], s[mt][nt][3]));
            }
        }
        #pragma unroll
        for (int mt = 0; mt < 2; mt++)
            #pragma unroll
            for (int r = 0; r < 2; r++) {
                pmax[mt][r] = fmaxf(pmax[mt][r], __shfl_xor_sync(0xffffffffu, pmax[mt][r], 1));
                pmax[mt][r] = fmaxf(pmax[mt][r], __shfl_xor_sync(0xffffffffu, pmax[mt][r], 2));
            }
        if (tg == 0) {
            #pragma unroll
            for (int mt = 0; mt < 2; mt++) {
                RED[wx * 64 + rl0_base + mt * 16 + g    ] = pmax[mt][0];
                RED[wx * 64 + rl0_base + mt * 16 + g + 8] = pmax[mt][1];
            }
        }
        __syncthreads();
        if (tid < 64) {
            float tm = fmaxf(fmaxf(RED[tid], RED[64 + tid]),
                             fmaxf(RED[128 + tid], RED[192 + tid]));
            float om = RMAX[tid];
            float nm = fmaxf(om, tm);
            float sc = __expf(om - nm);
            RMAX[tid] = nm;
            RSCL[tid] = sc;
            RSUM[tid] *= sc;
        }
        __syncthreads();

        // --- exp, write P (overwrites K buffer), partial row sums ---
        float psum[2][2] = {};
        #pragma unroll
        for (int mt = 0; mt < 2; mt++) {
            int rl0 = rl0_base + mt * 16 + g;
            float mx0 = RMAX[rl0], mx1 = RMAX[rl0 + 8];
            #pragma unroll
            for (int nt = 0; nt < 2; nt++) {
                int mc = wx * 16 + nt * 8 + 2 * tg;
                float p0 = __expf(s[mt][nt][0] - mx0);
                float p1 = __expf(s[mt][nt][1] - mx0);
                float p2 = __expf(s[mt][nt][2] - mx1);
                float p3 = __expf(s[mt][nt][3] - mx1);
                uint32_t hh, ll;
                split_tf32(p0, hh, ll); KPH[(mc  )*AT_STRIDE + rl0    ]=hh; KPL[(mc  )*AT_STRIDE + rl0    ]=ll;
                split_tf32(p1, hh, ll); KPH[(mc+1)*AT_STRIDE + rl0    ]=hh; KPL[(mc+1)*AT_STRIDE + rl0    ]=ll;
                split_tf32(p2, hh, ll); KPH[(mc  )*AT_STRIDE + rl0 + 8]=hh; KPL[(mc  )*AT_STRIDE + rl0 + 8]=ll;
                split_tf32(p3, hh, ll); KPH[(mc+1)*AT_STRIDE + rl0 + 8]=hh; KPL[(mc+1)*AT_STRIDE + rl0 + 8]=ll;
                psum[mt][0] += p0 + p1;
                psum[mt][1] += p2 + p3;
            }
        }
        #pragma unroll
        for (int mt = 0; mt < 2; mt++)
            #pragma unroll
            for (int r = 0; r < 2; r++) {
                psum[mt][r] += __shfl_xor_sync(0xffffffffu, psum[mt][r], 1);
                psum[mt][r] += __shfl_xor_sync(0xffffffffu, psum[mt][r], 2);
            }
        if (tg == 0) {
            #pragma unroll
            for (int mt = 0; mt < 2; mt++) {
                RED[wx * 64 + rl0_base + mt * 16 + g    ] = psum[mt][0];
                RED[wx * 64 + rl0_base + mt * 16 + g + 8] = psum[mt][1];
            }
        }
        __syncthreads();
        if (tid < 64)
            RSUM[tid] += RED[tid] + RED[64 + tid] + RED[128 + tid] + RED[192 + tid];

        // --- PV: O = O*scale + P·V  (warp tile: 32 n x 16 d) ---
        #pragma unroll
        for (int mt = 0; mt < 2; mt++) {
            int rl0 = rl0_base + mt * 16 + g;
            float sc0 = RSCL[rl0], sc1 = RSCL[rl0 + 8];
            #pragma unroll
            for (int nt = 0; nt < 2; nt++) {
                o[mt][nt][0] *= sc0; o[mt][nt][1] *= sc0;
                o[mt][nt][2] *= sc1; o[mt][nt][3] *= sc1;
            }
        }
        #pragma unroll
        for (int ks = 0; ks < 8; ks++) {
            const int kb = ks * 8;
            uint32_t ah[2][4], al[2][4], bh2[2][2], bl2[2][2];
            #pragma unroll
            for (int mt = 0; mt < 2; mt++) {
                int n = rl0_base + mt * 16;
                ah[mt][0]=KPH[(kb+tg  )*AT_STRIDE + n+g  ]; al[mt][0]=KPL[(kb+tg  )*AT_STRIDE + n+g  ];
                ah[mt][1]=KPH[(kb+tg  )*AT_STRIDE + n+g+8]; al[mt][1]=KPL[(kb+tg  )*AT_STRIDE + n+g+8];
                ah[mt][2]=KPH[(kb+tg+4)*AT_STRIDE + n+g  ]; al[mt][2]=KPL[(kb+tg+4)*AT_STRIDE + n+g  ];
                ah[mt][3]=KPH[(kb+tg+4)*AT_STRIDE + n+g+8]; al[mt][3]=KPL[(kb+tg+4)*AT_STRIDE + n+g+8];
            }
            #pragma unroll
            for (int nt = 0; nt < 2; nt++) {
                int d = wx * 16 + nt * 8 + g;
                bh2[nt][0]=VH[(kb+tg  )*AT_STRIDE + d]; bl2[nt][0]=VL[(kb+tg  )*AT_STRIDE + d];
                bh2[nt][1]=VH[(kb+tg+4)*AT_STRIDE + d]; bl2[nt][1]=VL[(kb+tg+4)*AT_STRIDE + d];
            }
            #pragma unroll
            for (int mt = 0; mt < 2; mt++)
                #pragma unroll
                for (int nt = 0; nt < 2; nt++)
                    mma3(o[mt][nt], ah[mt], al[mt], bh2[nt], bl2[nt]);
        }
    }

    __syncthreads();
    // --- epilogue: normalize and write msg[b, d*4+h, n] ---
    float* mp = g_msg + (size_t)b * Dd * Nn;
    #pragma unroll
    for (int mt = 0; mt < 2; mt++) {
        int rl0 = rl0_base + mt * 16 + g;
        float inv0 = 1.f / RSUM[rl0];
        float inv1 = 1.f / RSUM[rl0 + 8];
        int gn0 = n0 + rl0, gn1 = gn0 + 8;
        #pragma unroll
        for (int nt = 0; nt < 2; nt++) {
            int d = wx * 16 + nt * 8 + 2 * tg;
            mp[(size_t)(d       * Hh + h) * Nn + gn0] = o[mt][nt][0] * inv0;
            mp[(size_t)((d + 1) * Hh + h) * Nn + gn0] = o[mt][nt][1] * inv0;
            mp[(size_t)(d       * Hh + h) * Nn + gn1] = o[mt][nt][2] * inv1;
            mp[(size_t)((d + 1) * Hh + h) * Nn + gn1] = o[mt][nt][3] * inv1;
        }
    }
}

// ---------------------------------------------------------------------------
extern "C" void kernel_launch(void* const* d_in, const int* in_sizes, int n_in,
                              void* d_out, int out_size)
{
    const float* x      = (const float*)d_in[0];
    const float* source = (const float*)d_in[1];
    const float* mask   = (const float*)d_in[2];
    const float* Wq = (const float*)d_in[3];
    const float* bq = (const float*)d_in[4];
    const float* Wk = (const float*)d_in[5];
    const float* bk = (const float*)d_in[6];
    const float* Wv = (const float*)d_in[7];
    const float* bv = (const float*)d_in[8];
    const float* Wm = (const float*)d_in[9];
    const float* bm = (const float*)d_in[10];
    const float* W1 = (const float*)d_in[11];
    const float* b1 = (const float*)d_in[12];
    const float* gamma = (const float*)d_in[13];
    const float* beta  = (const float*)d_in[14];
    const float* rmean = (const float*)d_in[15];
    const float* rvar  = (const float*)d_in[16];
    const float* W2 = (const float*)d_in[17];
    const float* b2 = (const float*)d_in[18];
    float* out = (float*)d_out;

    float *qb, *kb, *vb, *msgb, *messageb, *hb;
    cudaGetSymbolAddress((void**)&qb, g_q);
    cudaGetSymbolAddress((void**)&kb, g_k);
    cudaGetSymbolAddress((void**)&vb, g_v);
    cudaGetSymbolAddress((void**)&msgb, g_msg);
    cudaGetSymbolAddress((void**)&messageb, g_message);
    cudaGetSymbolAddress((void**)&hb, g_h);

    const int SMEM_GEMM = 4 * 32 * SM_STRIDE * 4;
    const int SMEM_ATTN = ATTN_SMEM_WORDS * 4;

    cudaFuncSetAttribute(gemm_mma<256, 256, false, false>,
                         cudaFuncAttributeMaxDynamicSharedMemorySize, SMEM_GEMM);
    cudaFuncSetAttribute(gemm_mma<512, 512, true, true>,
                         cudaFuncAttributeMaxDynamicSharedMemorySize, SMEM_GEMM);
    cudaFuncSetAttribute(gemm_mma<256, 512, false, false>,
                         cudaFuncAttributeMaxDynamicSharedMemorySize, SMEM_GEMM);
    cudaFuncSetAttribute(attn_fused,
                         cudaFuncAttributeMaxDynamicSharedMemorySize, SMEM_ATTN);

    // q, k, v projections
    gemm_mma<256, 256, false, false><<<dim3(16, 2, 4), 256, SMEM_GEMM>>>(
        Wq, bq, x, nullptr, qb, nullptr, nullptr, nullptr, nullptr);
    gemm_mma<256, 256, false, false><<<dim3(16, 2, 4), 256, SMEM_GEMM>>>(
        Wk, bk, source, nullptr, kb, nullptr, nullptr, nullptr, nullptr);
    gemm_mma<256, 256, false, false><<<dim3(16, 2, 4), 256, SMEM_GEMM>>>(
        Wv, bv, source, nullptr, vb, nullptr, nullptr, nullptr, nullptr);

    // fused attention (scores + mask + softmax + PV)
    attn_fused<<<dim3(32, 1, 16), 256, SMEM_ATTN>>>(mask);

    // message projection
    gemm_mma<256, 256, false, false><<<dim3(16, 2, 4), 256, SMEM_GEMM>>>(
        Wm, bm, msgb, nullptr, messageb, nullptr, nullptr, nullptr, nullptr);

    // MLP layer 1 (concat[x, message]) + BN + ReLU
    gemm_mma<512, 512, true, true><<<dim3(16, 4, 4), 256, SMEM_GEMM>>>(
        W1, b1, x, messageb, hb, gamma, beta, rmean, rvar);

    // MLP layer 2 -> output
    gemm_mma<256, 512, false, false><<<dim3(16, 2, 4), 256, SMEM_GEMM>>>(
        W2, b2, hb, nullptr, out, nullptr, nullptr, nullptr, nullptr);
}

// round 8
// speedup vs baseline: 1.4653x; 1.4643x over previous
#include <cuda_runtime.h>
#include <math.h>
#include <float.h>
#include <stdint.h>

// Problem constants
#define Bn   4
#define Dd   256
#define Nn   2048
#define Mm   2048
#define Hh   4
#define DIMh 64

// Scratch (allocation-free: __device__ globals)
__device__ float g_q[Bn * Dd * Nn];
__device__ float g_k[Bn * Dd * Mm];
__device__ float g_v[Bn * Dd * Mm];
__device__ float g_msg[Bn * Dd * Nn];
__device__ float g_message[Bn * Dd * Nn];
__device__ float g_h[Bn * 2 * Dd * Nn];
__device__ float g_scores[(size_t)Bn * Hh * Nn * Mm];   // 268 MB

// ---------------------------------------------------------------------------
// bf16 split helpers: x = hi + lo, both bf16; pack two consecutive-k values
// into one u32 (lo half = even k).
// ---------------------------------------------------------------------------
__device__ __forceinline__ void pack_split(float f0, float f1, uint32_t& h, uint32_t& l)
{
    uint32_t hp;
    asm("cvt.rn.bf16x2.f32 %0, %1, %2;" : "=r"(hp) : "f"(f1), "f"(f0));
    float r0 = f0 - __uint_as_float(hp << 16);
    float r1 = f1 - __uint_as_float(hp & 0xffff0000u);
    uint32_t lp;
    asm("cvt.rn.bf16x2.f32 %0, %1, %2;" : "=r"(lp) : "f"(r1), "f"(r0));
    h = hp; l = lp;
}

__device__ __forceinline__ void mma_bf16(float (&d)[4],
                                         uint32_t a0, uint32_t a1, uint32_t a2, uint32_t a3,
                                         uint32_t b0, uint32_t b1)
{
    asm volatile(
        "mma.sync.aligned.m16n8k16.row.col.f32.bf16.bf16.f32 "
        "{%0,%1,%2,%3}, {%4,%5,%6,%7}, {%8,%9}, {%0,%1,%2,%3};\n"
        : "+f"(d[0]), "+f"(d[1]), "+f"(d[2]), "+f"(d[3])
        : "r"(a0), "r"(a1), "r"(a2), "r"(a3), "r"(b0), "r"(b1));
}

// 3-term compensated: acc += Ah*Bh + Ah*Bl + Al*Bh  (Al*Bl ~2^-18, dropped)
__device__ __forceinline__ void mma3(float (&d)[4],
                                     const uint32_t (&ah)[4], const uint32_t (&al)[4],
                                     const uint32_t (&bh)[2], const uint32_t (&bl)[2])
{
    mma_bf16(d, al[0], al[1], al[2], al[3], bh[0], bh[1]);
    mma_bf16(d, ah[0], ah[1], ah[2], ah[3], bl[0], bl[1]);
    mma_bf16(d, ah[0], ah[1], ah[2], ah[3], bh[0], bh[1]);
}

#define GST 20   // GEMM/PV tile stride (16 u32 + 4 pad): (20g+tg)%32 bijective
#define AST 36   // attention scores tile stride (32 u32 + 4 pad): (4g+tg)%32 bijective

// ---------------------------------------------------------------------------
// Generic per-batch 1x1-conv GEMM (bf16 3-term, m16n8k16):
//   Y[b,o,n] = sum_c W[o,c] * X[b,c,n] + bias[o]
// Block 128(o) x 128(n), K-chunk 32 channels (= 16 packed u32, 2 k16 steps),
// 8 warps (2x4), warp tile 64x32.
// ---------------------------------------------------------------------------
template<int OUTC, int INC, bool CONCAT, bool BNRELU>
__global__ void __launch_bounds__(256)
gemm_mma(const float* __restrict__ W, const float* __restrict__ bias,
         const float* __restrict__ X0, const float* __restrict__ X1,
         float* __restrict__ Y,
         const float* __restrict__ gamma, const float* __restrict__ beta,
         const float* __restrict__ rmean, const float* __restrict__ rvar)
{
    __shared__ uint32_t AsH[128][GST], AsL[128][GST];   // [o][c-pair]
    __shared__ uint32_t BsH[128][GST], BsL[128][GST];   // [n][c-pair]

    const int tid = threadIdx.x;
    const int n0 = blockIdx.x * 128;
    const int o0 = blockIdx.y * 128;
    const int b  = blockIdx.z;
    const int XC = CONCAT ? (INC / 2) : INC;
    const float* x0 = X0 + (size_t)b * XC * Nn;
    const float* x1 = CONCAT ? (X1 + (size_t)b * XC * Nn) : nullptr;

    const int w      = tid >> 5;
    const int lane   = tid & 31;
    const int g      = lane >> 2;
    const int tg     = lane & 3;
    const int warp_m = w >> 2;
    const int warp_n = w & 3;

    float acc[4][4][4] = {};

    const int o_ld  = tid >> 1;          // 0..127
    const int half  = tid & 1;           // 16 c each
    const int cp_ld = tid >> 4;          // 0..15 (c-pair within chunk)
    const int nb_ld = tid & 15;

    for (int c0 = 0; c0 < INC; c0 += 32) {
        // --- W tile: AsH/L[o][cp], packed along c ---
        {
            const float* wp = W + (size_t)(o0 + o_ld) * INC + c0 + half * 16;
            #pragma unroll
            for (int q = 0; q < 2; q++) {
                float4 u = *(const float4*)(wp + q * 8);
                float4 v = *(const float4*)(wp + q * 8 + 4);
                int cb = half * 8 + q * 4;
                pack_split(u.x, u.y, AsH[o_ld][cb + 0], AsL[o_ld][cb + 0]);
                pack_split(u.z, u.w, AsH[o_ld][cb + 1], AsL[o_ld][cb + 1]);
                pack_split(v.x, v.y, AsH[o_ld][cb + 2], AsL[o_ld][cb + 2]);
                pack_split(v.z, v.w, AsH[o_ld][cb + 3], AsL[o_ld][cb + 3]);
            }
        }
        // --- X tile (transposed pack): BsH/L[n][cp] ---
        {
            int c = c0 + 2 * cp_ld;
            const float *xr0, *xr1;
            if (!CONCAT || c < INC / 2) {
                xr0 = x0 + (size_t)c * Nn;
                xr1 = x0 + (size_t)(c + 1) * Nn;
            } else {
                xr0 = x1 + (size_t)(c - INC / 2) * Nn;
                xr1 = x1 + (size_t)(c + 1 - INC / 2) * Nn;
            }
            #pragma unroll
            for (int i = 0; i < 8; i++) {
                int n = nb_ld + 16 * i;
                pack_split(xr0[n0 + n], xr1[n0 + n], BsH[n][cp_ld], BsL[n][cp_ld]);
            }
        }
        __syncthreads();

        #pragma unroll
        for (int st = 0; st < 2; st++) {
            const int kc = st * 8;
            uint32_t ah[4][4], al[4][4], bh[4][2], bl[4][2];
            #pragma unroll
            for (int mt = 0; mt < 4; mt++) {
                int m = warp_m * 64 + mt * 16;
                ah[mt][0]=AsH[m+g  ][kc+tg  ]; al[mt][0]=AsL[m+g  ][kc+tg  ];
                ah[mt][1]=AsH[m+g+8][kc+tg  ]; al[mt][1]=AsL[m+g+8][kc+tg  ];
                ah[mt][2]=AsH[m+g  ][kc+tg+4]; al[mt][2]=AsL[m+g  ][kc+tg+4];
                ah[mt][3]=AsH[m+g+8][kc+tg+4]; al[mt][3]=AsL[m+g+8][kc+tg+4];
            }
            #pragma unroll
            for (int nt = 0; nt < 4; nt++) {
                int n = warp_n * 32 + nt * 8 + g;
                bh[nt][0]=BsH[n][kc+tg  ]; bl[nt][0]=BsL[n][kc+tg  ];
                bh[nt][1]=BsH[n][kc+tg+4]; bl[nt][1]=BsL[n][kc+tg+4];
            }
            #pragma unroll
            for (int mt = 0; mt < 4; mt++)
                #pragma unroll
                for (int nt = 0; nt < 4; nt++)
                    mma3(acc[mt][nt], ah[mt], al[mt], bh[nt], bl[nt]);
        }
        __syncthreads();
    }

    // --- epilogue ---
    float* yb = Y + (size_t)b * OUTC * Nn;
    #pragma unroll
    for (int mt = 0; mt < 4; mt++) {
        int r0 = o0 + warp_m * 64 + mt * 16 + g;
        int r1 = r0 + 8;
        float bv0 = bias[r0], bv1 = bias[r1];
        float sc0 = 1.f, sh0 = 0.f, sc1 = 1.f, sh1 = 0.f;
        if (BNRELU) {
            float rs0 = rsqrtf(rvar[r0] + 1e-3f);
            sc0 = gamma[r0] * rs0; sh0 = beta[r0] - rmean[r0] * sc0;
            float rs1 = rsqrtf(rvar[r1] + 1e-3f);
            sc1 = gamma[r1] * rs1; sh1 = beta[r1] - rmean[r1] * sc1;
        }
        #pragma unroll
        for (int nt = 0; nt < 4; nt++) {
            int n = n0 + warp_n * 32 + nt * 8 + 2 * tg;
            float t0 = acc[mt][nt][0] + bv0;
            float t1 = acc[mt][nt][1] + bv0;
            float t2 = acc[mt][nt][2] + bv1;
            float t3 = acc[mt][nt][3] + bv1;
            if (BNRELU) {
                t0 = fmaxf(t0 * sc0 + sh0, 0.f);
                t1 = fmaxf(t1 * sc0 + sh0, 0.f);
                t2 = fmaxf(t2 * sc1 + sh1, 0.f);
                t3 = fmaxf(t3 * sc1 + sh1, 0.f);
            }
            *(float2*)&yb[(size_t)r0 * Nn + n] = make_float2(t0, t1);
            *(float2*)&yb[(size_t)r1 * Nn + n] = make_float2(t2, t3);
        }
    }
}

// ---------------------------------------------------------------------------
// Attention scores (bf16 3-term):
//   S[bh,n,m] = (1/8) * sum_d q[b,d*4+h,n] * k[b,d*4+h,m], masked -> -FLT_MAX
// Block 128(n) x 128(m). Whole d=64 loaded once (32 u32 packed), 4 k16 steps.
// ---------------------------------------------------------------------------
__global__ void __launch_bounds__(256)
attn_scores_mma(const float* __restrict__ mask)
{
    extern __shared__ uint32_t sm[];
    uint32_t* QH = sm;                    // [128 n][AST]
    uint32_t* QL = sm + 128 * AST;
    uint32_t* KH = sm + 2 * 128 * AST;    // [128 m][AST]
    uint32_t* KL = sm + 3 * 128 * AST;

    const int tid = threadIdx.x;
    const int m0 = blockIdx.x * 128;
    const int n0 = blockIdx.y * 128;
    const int bh = blockIdx.z;
    const int b = bh >> 2, h = bh & 3;
    const float* qg = g_q + (size_t)b * Dd * Nn;
    const float* kg = g_k + (size_t)b * Dd * Mm;

    const int w      = tid >> 5;
    const int lane   = tid & 31;
    const int g      = lane >> 2;
    const int tg     = lane & 3;
    const int warp_m = w >> 2;
    const int warp_n = w & 3;

    float acc[4][4][4] = {};

    // loaders: dp-pair index + strided n
    const int dpg = tid >> 4;   // 0..15
    const int nbl = tid & 15;

    #pragma unroll
    for (int hf = 0; hf < 2; hf++) {
        int dp  = dpg + 16 * hf;           // 0..31 (d-pair)
        int ch0 = (2 * dp) * Hh + h;
        const float* q0 = qg + (size_t)ch0 * Nn + n0;
        const float* q1 = qg + (size_t)(ch0 + Hh) * Nn + n0;
        const float* k0 = kg + (size_t)ch0 * Mm + m0;
        const float* k1 = kg + (size_t)(ch0 + Hh) * Mm + m0;
        #pragma unroll
        for (int i = 0; i < 8; i++) {
            int n = nbl + 16 * i;
            pack_split(q0[n], q1[n], QH[n * AST + dp], QL[n * AST + dp]);
            pack_split(k0[n], k1[n], KH[n * AST + dp], KL[n * AST + dp]);
        }
    }
    __syncthreads();

    #pragma unroll
    for (int st = 0; st < 4; st++) {
        const int kc = st * 8;
        uint32_t ah[4][4], al[4][4], bh2[4][2], bl2[4][2];
        #pragma unroll
        for (int mt = 0; mt < 4; mt++) {
            int n = warp_m * 64 + mt * 16;
            ah[mt][0]=QH[(n+g  )*AST + kc+tg  ]; al[mt][0]=QL[(n+g  )*AST + kc+tg  ];
            ah[mt][1]=QH[(n+g+8)*AST + kc+tg  ]; al[mt][1]=QL[(n+g+8)*AST + kc+tg  ];
            ah[mt][2]=QH[(n+g  )*AST + kc+tg+4]; al[mt][2]=QL[(n+g  )*AST + kc+tg+4];
            ah[mt][3]=QH[(n+g+8)*AST + kc+tg+4]; al[mt][3]=QL[(n+g+8)*AST + kc+tg+4];
        }
        #pragma unroll
        for (int nt = 0; nt < 4; nt++) {
            int m = warp_n * 32 + nt * 8 + g;
            bh2[nt][0]=KH[m*AST + kc+tg  ]; bl2[nt][0]=KL[m*AST + kc+tg  ];
            bh2[nt][1]=KH[m*AST + kc+tg+4]; bl2[nt][1]=KL[m*AST + kc+tg+4];
        }
        #pragma unroll
        for (int mt = 0; mt < 4; mt++)
            #pragma unroll
            for (int nt = 0; nt < 4; nt++)
                mma3(acc[mt][nt], ah[mt], al[mt], bh2[nt], bl2[nt]);
    }

    float* sp = g_scores + (size_t)bh * Nn * Mm;
    #pragma unroll
    for (int mt = 0; mt < 4; mt++) {
        int nr0 = n0 + warp_m * 64 + mt * 16 + g;
        int nr1 = nr0 + 8;
        #pragma unroll
        for (int nt = 0; nt < 4; nt++) {
            int m = m0 + warp_n * 32 + nt * 8 + 2 * tg;
            float2 mk0 = *(const float2*)&mask[((size_t)b * Nn + nr0) * Mm + m];
            float2 mk1 = *(const float2*)&mask[((size_t)b * Nn + nr1) * Mm + m];
            float s0 = (mk0.x > 0.f) ? acc[mt][nt][0] * 0.125f : -FLT_MAX;
            float s1 = (mk0.y > 0.f) ? acc[mt][nt][1] * 0.125f : -FLT_MAX;
            float s2 = (mk1.x > 0.f) ? acc[mt][nt][2] * 0.125f : -FLT_MAX;
            float s3 = (mk1.y > 0.f) ? acc[mt][nt][3] * 0.125f : -FLT_MAX;
            *(float2*)&sp[(size_t)nr0 * Mm + m] = make_float2(s0, s1);
            *(float2*)&sp[(size_t)nr1 * Mm + m] = make_float2(s2, s3);
        }
    }
}

// ---------------------------------------------------------------------------
// Row-wise softmax over M=2048 in-place on g_scores. One block per row.
// ---------------------------------------------------------------------------
__global__ void __launch_bounds__(256)
softmax_rows()
{
    const int row = blockIdx.x;
    float4* p = (float4*)(g_scores + (size_t)row * Mm);
    const int tid = threadIdx.x;
    __shared__ float red[256];

    float4 v[2];
    float mx = -FLT_MAX;
    #pragma unroll
    for (int r = 0; r < 2; r++) {
        v[r] = p[tid + 256 * r];
        mx = fmaxf(mx, fmaxf(fmaxf(v[r].x, v[r].y), fmaxf(v[r].z, v[r].w)));
    }
    red[tid] = mx;
    __syncthreads();
    for (int s = 128; s > 0; s >>= 1) {
        if (tid < s) red[tid] = fmaxf(red[tid], red[tid + s]);
        __syncthreads();
    }
    mx = red[0];
    __syncthreads();

    float sum = 0.f;
    #pragma unroll
    for (int r = 0; r < 2; r++) {
        v[r].x = __expf(v[r].x - mx);
        v[r].y = __expf(v[r].y - mx);
        v[r].z = __expf(v[r].z - mx);
        v[r].w = __expf(v[r].w - mx);
        sum += v[r].x + v[r].y + v[r].z + v[r].w;
    }
    red[tid] = sum;
    __syncthreads();
    for (int s = 128; s > 0; s >>= 1) {
        if (tid < s) red[tid] += red[tid + s];
        __syncthreads();
    }
    float inv = 1.f / red[0];
    #pragma unroll
    for (int r = 0; r < 2; r++) {
        v[r].x *= inv; v[r].y *= inv; v[r].z *= inv; v[r].w *= inv;
        p[tid + 256 * r] = v[r];
    }
}

// ---------------------------------------------------------------------------
// PV (bf16 3-term): msg[b, d*4+h, n] = sum_m P[bh,n,m] * v[b, d*4+h, m]
// Block 64(d) x 128(n); m streamed in chunks of 32 (16 packed u32, 2 k16 steps).
// ---------------------------------------------------------------------------
__global__ void __launch_bounds__(256)
attn_pv_mma()
{
    __shared__ uint32_t VHs[64][GST],  VLs[64][GST];    // [d][m-pair]
    __shared__ uint32_t PHs[128][GST], PLs[128][GST];   // [n][m-pair]

    const int tid = threadIdx.x;
    const int n0 = blockIdx.x * 128;
    const int bh = blockIdx.z;
    const int b = bh >> 2, h = bh & 3;
    const float* vg = g_v + (size_t)b * Dd * Mm;
    const float* P  = g_scores + (size_t)bh * Nn * Mm;

    const int w      = tid >> 5;
    const int lane   = tid & 31;
    const int g      = lane >> 2;
    const int tg     = lane & 3;
    const int warp_m = w >> 2;   // d half
    const int warp_n = w & 3;

    float acc[2][4][4] = {};

    const int vd = tid >> 2;          // 0..63
    const int vq = tid & 3;           // 8 m each
    const int pn = tid >> 1;          // 0..127
    const int ph = tid & 1;           // 16 m each

    for (int m0 = 0; m0 < Mm; m0 += 32) {
        // V tile: VHs/L[d][mp]
        {
            const float* vp = vg + (size_t)(vd * Hh + h) * Mm + m0 + vq * 8;
            float4 u = *(const float4*)(vp);
            float4 v4 = *(const float4*)(vp + 4);
            int cb = vq * 4;
            pack_split(u.x,  u.y,  VHs[vd][cb + 0], VLs[vd][cb + 0]);
            pack_split(u.z,  u.w,  VHs[vd][cb + 1], VLs[vd][cb + 1]);
            pack_split(v4.x, v4.y, VHs[vd][cb + 2], VLs[vd][cb + 2]);
            pack_split(v4.z, v4.w, VHs[vd][cb + 3], VLs[vd][cb + 3]);
        }
        // P tile: PHs/L[n][mp]
        {
            const float* pp = P + (size_t)(n0 + pn) * Mm + m0 + ph * 16;
            #pragma unroll
            for (int q = 0; q < 2; q++) {
                float4 u = *(const float4*)(pp + q * 8);
                float4 v4 = *(const float4*)(pp + q * 8 + 4);
                int cb = ph * 8 + q * 4;
                pack_split(u.x,  u.y,  PHs[pn][cb + 0], PLs[pn][cb + 0]);
                pack_split(u.z,  u.w,  PHs[pn][cb + 1], PLs[pn][cb + 1]);
                pack_split(v4.x, v4.y, PHs[pn][cb + 2], PLs[pn][cb + 2]);
                pack_split(v4.z, v4.w, PHs[pn][cb + 3], PLs[pn][cb + 3]);
            }
        }
        __syncthreads();

        #pragma unroll
        for (int st = 0; st < 2; st++) {
            const int kc = st * 8;
            uint32_t ah[2][4], al[2][4], bh2[4][2], bl2[4][2];
            #pragma unroll
            for (int mt = 0; mt < 2; mt++) {
                int d = warp_m * 32 + mt * 16;
                ah[mt][0]=VHs[d+g  ][kc+tg  ]; al[mt][0]=VLs[d+g  ][kc+tg  ];
                ah[mt][1]=VHs[d+g+8][kc+tg  ]; al[mt][1]=VLs[d+g+8][kc+tg  ];
                ah[mt][2]=VHs[d+g  ][kc+tg+4]; al[mt][2]=VLs[d+g  ][kc+tg+4];
                ah[mt][3]=VHs[d+g+8][kc+tg+4]; al[mt][3]=VLs[d+g+8][kc+tg+4];
            }
            #pragma unroll
            for (int nt = 0; nt < 4; nt++) {
                int n = warp_n * 32 + nt * 8 + g;
                bh2[nt][0]=PHs[n][kc+tg  ]; bl2[nt][0]=PLs[n][kc+tg  ];
                bh2[nt][1]=PHs[n][kc+tg+4]; bl2[nt][1]=PLs[n][kc+tg+4];
            }
            #pragma unroll
            for (int mt = 0; mt < 2; mt++)
                #pragma unroll
                for (int nt = 0; nt < 4; nt++)
                    mma3(acc[mt][nt], ah[mt], al[mt], bh2[nt], bl2[nt]);
        }
        __syncthreads();
    }

    float* mp = g_msg + (size_t)b * Dd * Nn;
    #pragma unroll
    for (int mt = 0; mt < 2; mt++) {
        int d0 = warp_m * 32 + mt * 16 + g;
        int d1 = d0 + 8;
        #pragma unroll
        for (int nt = 0; nt < 4; nt++) {
            int n = n0 + warp_n * 32 + nt * 8 + 2 * tg;
            *(float2*)&mp[(size_t)(d0 * Hh + h) * Nn + n] =
                make_float2(acc[mt][nt][0], acc[mt][nt][1]);
            *(float2*)&mp[(size_t)(d1 * Hh + h) * Nn + n] =
                make_float2(acc[mt][nt][2], acc[mt][nt][3]);
        }
    }
}

// ---------------------------------------------------------------------------
extern "C" void kernel_launch(void* const* d_in, const int* in_sizes, int n_in,
                              void* d_out, int out_size)
{
    const float* x      = (const float*)d_in[0];
    const float* source = (const float*)d_in[1];
    const float* mask   = (const float*)d_in[2];
    const float* Wq = (const float*)d_in[3];
    const float* bq = (const float*)d_in[4];
    const float* Wk = (const float*)d_in[5];
    const float* bk = (const float*)d_in[6];
    const float* Wv = (const float*)d_in[7];
    const float* bv = (const float*)d_in[8];
    const float* Wm = (const float*)d_in[9];
    const float* bm = (const float*)d_in[10];
    const float* W1 = (const float*)d_in[11];
    const float* b1 = (const float*)d_in[12];
    const float* gamma = (const float*)d_in[13];
    const float* beta  = (const float*)d_in[14];
    const float* rmean = (const float*)d_in[15];
    const float* rvar  = (const float*)d_in[16];
    const float* W2 = (const float*)d_in[17];
    const float* b2 = (const float*)d_in[18];
    float* out = (float*)d_out;

    float *qb, *kb, *vb, *msgb, *messageb, *hb;
    cudaGetSymbolAddress((void**)&qb, g_q);
    cudaGetSymbolAddress((void**)&kb, g_k);
    cudaGetSymbolAddress((void**)&vb, g_v);
    cudaGetSymbolAddress((void**)&msgb, g_msg);
    cudaGetSymbolAddress((void**)&messageb, g_message);
    cudaGetSymbolAddress((void**)&hb, g_h);

    const int SMEM_SCORES = 4 * 128 * AST * 4;   // 73728 B
    cudaFuncSetAttribute(attn_scores_mma,
                         cudaFuncAttributeMaxDynamicSharedMemorySize, SMEM_SCORES);

    // q, k, v projections
    gemm_mma<256, 256, false, false><<<dim3(16, 2, 4), 256>>>(
        Wq, bq, x, nullptr, qb, nullptr, nullptr, nullptr, nullptr);
    gemm_mma<256, 256, false, false><<<dim3(16, 2, 4), 256>>>(
        Wk, bk, source, nullptr, kb, nullptr, nullptr, nullptr, nullptr);
    gemm_mma<256, 256, false, false><<<dim3(16, 2, 4), 256>>>(
        Wv, bv, source, nullptr, vb, nullptr, nullptr, nullptr, nullptr);

    // attention
    attn_scores_mma<<<dim3(16, 16, 16), 256, SMEM_SCORES>>>(mask);
    softmax_rows<<<Bn * Hh * Nn, 256>>>();
    attn_pv_mma<<<dim3(16, 1, 16), 256>>>();

    // message projection
    gemm_mma<256, 256, false, false><<<dim3(16, 2, 4), 256>>>(
        Wm, bm, msgb, nullptr, messageb, nullptr, nullptr, nullptr, nullptr);

    // MLP layer 1 (concat[x, message]) + BN + ReLU
    gemm_mma<512, 512, true, true><<<dim3(16, 4, 4), 256>>>(
        W1, b1, x, messageb, hb, gamma, beta, rmean, rvar);

    // MLP layer 2 -> output
    gemm_mma<256, 512, false, false><<<dim3(16, 2, 4), 256>>>(
        W2, b2, hb, nullptr, out, nullptr, nullptr, nullptr, nullptr);
}

// round 9
// speedup vs baseline: 1.6224x; 1.1072x over previous
#include <cuda_runtime.h>
#include <math.h>
#include <float.h>
#include <stdint.h>

// Problem constants
#define Bn   4
#define Dd   256
#define Nn   2048
#define Mm   2048
#define Hh   4
#define DIMh 64

// Scratch (allocation-free: __device__ globals)
__device__ float g_q[Bn * Dd * Nn];
__device__ float g_k[Bn * Dd * Mm];
__device__ float g_v[Bn * Dd * Mm];
__device__ float g_msg[Bn * Dd * Nn];
__device__ float g_message[Bn * Dd * Nn];
__device__ float g_h[Bn * 2 * Dd * Nn];
// P_unnorm planes, packed bf16x2 along m (hi/lo split)
__device__ uint32_t g_ph[(size_t)Bn * Hh * Nn * Mm / 2];   // 134 MB
__device__ uint32_t g_pl[(size_t)Bn * Hh * Nn * Mm / 2];   // 134 MB
__device__ float g_psum[(size_t)Bn * Hh * Nn * 32];        // per-(row, m-tile) partials
__device__ float g_rowsum[Bn * Hh * Nn];

// ---------------------------------------------------------------------------
// bf16 split helpers: x = hi + lo, both bf16; pack two consecutive-k values
// into one u32 (lo half = even k).
// ---------------------------------------------------------------------------
__device__ __forceinline__ void pack_split(float f0, float f1, uint32_t& h, uint32_t& l)
{
    uint32_t hp;
    asm("cvt.rn.bf16x2.f32 %0, %1, %2;" : "=r"(hp) : "f"(f1), "f"(f0));
    float r0 = f0 - __uint_as_float(hp << 16);
    float r1 = f1 - __uint_as_float(hp & 0xffff0000u);
    uint32_t lp;
    asm("cvt.rn.bf16x2.f32 %0, %1, %2;" : "=r"(lp) : "f"(r1), "f"(r0));
    h = hp; l = lp;
}

__device__ __forceinline__ void mma_bf16(float (&d)[4],
                                         uint32_t a0, uint32_t a1, uint32_t a2, uint32_t a3,
                                         uint32_t b0, uint32_t b1)
{
    asm volatile(
        "mma.sync.aligned.m16n8k16.row.col.f32.bf16.bf16.f32 "
        "{%0,%1,%2,%3}, {%4,%5,%6,%7}, {%8,%9}, {%0,%1,%2,%3};\n"
        : "+f"(d[0]), "+f"(d[1]), "+f"(d[2]), "+f"(d[3])
        : "r"(a0), "r"(a1), "r"(a2), "r"(a3), "r"(b0), "r"(b1));
}

__device__ __forceinline__ void mma3(float (&d)[4],
                                     const uint32_t (&ah)[4], const uint32_t (&al)[4],
                                     const uint32_t (&bh)[2], const uint32_t (&bl)[2])
{
    mma_bf16(d, al[0], al[1], al[2], al[3], bh[0], bh[1]);
    mma_bf16(d, ah[0], ah[1], ah[2], ah[3], bl[0], bl[1]);
    mma_bf16(d, ah[0], ah[1], ah[2], ah[3], bh[0], bh[1]);
}

#define GST 20   // GEMM/PV tile stride (16 u32 + 4 pad)
#define AST 36   // scores tile stride (32 u32 + 4 pad)

// ---------------------------------------------------------------------------
// 1x1-conv GEMM (bf16 3-term): Y[b,o,n] = sum_c W[o,c]*X[b,c,n] + bias[o]
// Block 64(o) x 128(n), K-chunk 32 channels, 8 warps (2x4), warp tile 32x32.
// ---------------------------------------------------------------------------
template<int OUTC, int INC, bool CONCAT, bool BNRELU>
__global__ void __launch_bounds__(256)
gemm_mma(const float* __restrict__ W, const float* __restrict__ bias,
         const float* __restrict__ X0, const float* __restrict__ X1,
         float* __restrict__ Y,
         const float* __restrict__ gamma, const float* __restrict__ beta,
         const float* __restrict__ rmean, const float* __restrict__ rvar)
{
    __shared__ uint32_t AsH[64][GST],  AsL[64][GST];    // [o][c-pair]
    __shared__ uint32_t BsH[128][GST], BsL[128][GST];   // [n][c-pair]

    const int tid = threadIdx.x;
    const int n0 = blockIdx.x * 128;
    const int o0 = blockIdx.y * 64;
    const int b  = blockIdx.z;
    const int XC = CONCAT ? (INC / 2) : INC;
    const float* x0 = X0 + (size_t)b * XC * Nn;
    const float* x1 = CONCAT ? (X1 + (size_t)b * XC * Nn) : nullptr;

    const int w      = tid >> 5;
    const int lane   = tid & 31;
    const int g      = lane >> 2;
    const int tg     = lane & 3;
    const int warp_m = w >> 2;
    const int warp_n = w & 3;

    float acc[2][4][4] = {};

    const int o_ld  = tid >> 2;          // 0..63
    const int q4    = tid & 3;           // 4 u32 (8 floats) each
    const int cp_ld = tid >> 4;          // 0..15
    const int nb_ld = tid & 15;

    for (int c0 = 0; c0 < INC; c0 += 32) {
        // --- W tile: AsH/L[o][cp] ---
        {
            const float* wp = W + (size_t)(o0 + o_ld) * INC + c0 + q4 * 8;
            float4 u = *(const float4*)(wp);
            float4 v = *(const float4*)(wp + 4);
            uint4 hh, ll;
            pack_split(u.x, u.y, hh.x, ll.x);
            pack_split(u.z, u.w, hh.y, ll.y);
            pack_split(v.x, v.y, hh.z, ll.z);
            pack_split(v.z, v.w, hh.w, ll.w);
            *(uint4*)&AsH[o_ld][q4 * 4] = hh;
            *(uint4*)&AsL[o_ld][q4 * 4] = ll;
        }
        // --- X tile (transposed pack): BsH/L[n][cp] ---
        {
            int c = c0 + 2 * cp_ld;
            const float *xr0, *xr1;
            if (!CONCAT || c < INC / 2) {
                xr0 = x0 + (size_t)c * Nn;
                xr1 = x0 + (size_t)(c + 1) * Nn;
            } else {
                xr0 = x1 + (size_t)(c - INC / 2) * Nn;
                xr1 = x1 + (size_t)(c + 1 - INC / 2) * Nn;
            }
            #pragma unroll
            for (int i = 0; i < 8; i++) {
                int n = nb_ld + 16 * i;
                pack_split(xr0[n0 + n], xr1[n0 + n], BsH[n][cp_ld], BsL[n][cp_ld]);
            }
        }
        __syncthreads();

        #pragma unroll
        for (int st = 0; st < 2; st++) {
            const int kc = st * 8;
            uint32_t ah[2][4], al[2][4], bh[4][2], bl[4][2];
            #pragma unroll
            for (int mt = 0; mt < 2; mt++) {
                int m = warp_m * 32 + mt * 16;
                ah[mt][0]=AsH[m+g  ][kc+tg  ]; al[mt][0]=AsL[m+g  ][kc+tg  ];
                ah[mt][1]=AsH[m+g+8][kc+tg  ]; al[mt][1]=AsL[m+g+8][kc+tg  ];
                ah[mt][2]=AsH[m+g  ][kc+tg+4]; al[mt][2]=AsL[m+g  ][kc+tg+4];
                ah[mt][3]=AsH[m+g+8][kc+tg+4]; al[mt][3]=AsL[m+g+8][kc+tg+4];
            }
            #pragma unroll
            for (int nt = 0; nt < 4; nt++) {
                int n = warp_n * 32 + nt * 8 + g;
                bh[nt][0]=BsH[n][kc+tg  ]; bl[nt][0]=BsL[n][kc+tg  ];
                bh[nt][1]=BsH[n][kc+tg+4]; bl[nt][1]=BsL[n][kc+tg+4];
            }
            #pragma unroll
            for (int mt = 0; mt < 2; mt++)
                #pragma unroll
                for (int nt = 0; nt < 4; nt++)
                    mma3(acc[mt][nt], ah[mt], al[mt], bh[nt], bl[nt]);
        }
        __syncthreads();
    }

    // --- epilogue ---
    float* yb = Y + (size_t)b * OUTC * Nn;
    #pragma unroll
    for (int mt = 0; mt < 2; mt++) {
        int r0 = o0 + warp_m * 32 + mt * 16 + g;
        int r1 = r0 + 8;
        float bv0 = bias[r0], bv1 = bias[r1];
        float sc0 = 1.f, sh0 = 0.f, sc1 = 1.f, sh1 = 0.f;
        if (BNRELU) {
            float rs0 = rsqrtf(rvar[r0] + 1e-3f);
            sc0 = gamma[r0] * rs0; sh0 = beta[r0] - rmean[r0] * sc0;
            float rs1 = rsqrtf(rvar[r1] + 1e-3f);
            sc1 = gamma[r1] * rs1; sh1 = beta[r1] - rmean[r1] * sc1;
        }
        #pragma unroll
        for (int nt = 0; nt < 4; nt++) {
            int n = n0 + warp_n * 32 + nt * 8 + 2 * tg;
            float t0 = acc[mt][nt][0] + bv0;
            float t1 = acc[mt][nt][1] + bv0;
            float t2 = acc[mt][nt][2] + bv1;
            float t3 = acc[mt][nt][3] + bv1;
            if (BNRELU) {
                t0 = fmaxf(t0 * sc0 + sh0, 0.f);
                t1 = fmaxf(t1 * sc0 + sh0, 0.f);
                t2 = fmaxf(t2 * sc1 + sh1, 0.f);
                t3 = fmaxf(t3 * sc1 + sh1, 0.f);
            }
            *(float2*)&yb[(size_t)r0 * Nn + n] = make_float2(t0, t1);
            *(float2*)&yb[(size_t)r1 * Nn + n] = make_float2(t2, t3);
        }
    }
}

// ---------------------------------------------------------------------------
// Scores + mask + exp (no max subtraction; |s| <~ 5 so exp is safe):
//   P_unnorm[bh,n,m] = mask ? exp(q·k/8) : 0,  written packed bf16 hi/lo.
// Also writes per-(row, m-tile) partial sums (deterministic, no atomics).
// Block 128(n) x 64(m); warps 2(n) x 4(m); warp tile 64n x 16m.
// ---------------------------------------------------------------------------
__global__ void __launch_bounds__(256)
attn_scores_p(const float* __restrict__ mask)
{
    extern __shared__ uint32_t sm[];
    uint32_t* QH = sm;                                  // [128][AST]
    uint32_t* QL = sm + 128 * AST;
    uint32_t* KH = sm + 2 * 128 * AST;                  // [64][AST]
    uint32_t* KL = sm + 2 * 128 * AST + 64 * AST;
    float* RED   = (float*)(sm + 2 * 128 * AST + 2 * 64 * AST);  // [4][128]

    const int tid = threadIdx.x;
    const int m0 = blockIdx.x * 64;
    const int n0 = blockIdx.y * 128;
    const int bh = blockIdx.z;
    const int b = bh >> 2, h = bh & 3;
    const float* qg = g_q + (size_t)b * Dd * Nn;
    const float* kg = g_k + (size_t)b * Dd * Mm;

    const int w      = tid >> 5;
    const int lane   = tid & 31;
    const int g      = lane >> 2;
    const int tg     = lane & 3;
    const int warp_m = w >> 2;   // n half
    const int warp_n = w & 3;    // m quarter (16 m)

    float acc[4][2][4] = {};

    const int dpg = tid >> 4;   // 0..15
    const int cbl = tid & 15;

    #pragma unroll
    for (int hf = 0; hf < 2; hf++) {
        int dp  = dpg + 16 * hf;           // d-pair 0..31
        int ch0 = (2 * dp) * Hh + h;
        const float* q0 = qg + (size_t)ch0 * Nn + n0;
        const float* q1 = qg + (size_t)(ch0 + Hh) * Nn + n0;
        const float* k0 = kg + (size_t)ch0 * Mm + m0;
        const float* k1 = kg + (size_t)(ch0 + Hh) * Mm + m0;
        #pragma unroll
        for (int i = 0; i < 8; i++) {
            int n = cbl + 16 * i;
            pack_split(q0[n], q1[n], QH[n * AST + dp], QL[n * AST + dp]);
        }
        #pragma unroll
        for (int i = 0; i < 4; i++) {
            int m = cbl + 16 * i;
            pack_split(k0[m], k1[m], KH[m * AST + dp], KL[m * AST + dp]);
        }
    }
    __syncthreads();

    #pragma unroll
    for (int st = 0; st < 4; st++) {
        const int kc = st * 8;
        uint32_t ah[4][4], al[4][4], bh2[2][2], bl2[2][2];
        #pragma unroll
        for (int mt = 0; mt < 4; mt++) {
            int n = warp_m * 64 + mt * 16;
            ah[mt][0]=QH[(n+g  )*AST + kc+tg  ]; al[mt][0]=QL[(n+g  )*AST + kc+tg  ];
            ah[mt][1]=QH[(n+g+8)*AST + kc+tg  ]; al[mt][1]=QL[(n+g+8)*AST + kc+tg  ];
            ah[mt][2]=QH[(n+g  )*AST + kc+tg+4]; al[mt][2]=QL[(n+g  )*AST + kc+tg+4];
            ah[mt][3]=QH[(n+g+8)*AST + kc+tg+4]; al[mt][3]=QL[(n+g+8)*AST + kc+tg+4];
        }
        #pragma unroll
        for (int nt = 0; nt < 2; nt++) {
            int m = warp_n * 16 + nt * 8 + g;
            bh2[nt][0]=KH[m*AST + kc+tg  ]; bl2[nt][0]=KL[m*AST + kc+tg  ];
            bh2[nt][1]=KH[m*AST + kc+tg+4]; bl2[nt][1]=KL[m*AST + kc+tg+4];
        }
        #pragma unroll
        for (int mt = 0; mt < 4; mt++)
            #pragma unroll
            for (int nt = 0; nt < 2; nt++)
                mma3(acc[mt][nt], ah[mt], al[mt], bh2[nt], bl2[nt]);
    }

    // --- epilogue: mask, exp, pack-store P, partial row sums ---
    float rsum[4][2];
    #pragma unroll
    for (int mt = 0; mt < 4; mt++) { rsum[mt][0] = 0.f; rsum[mt][1] = 0.f; }

    #pragma unroll
    for (int mt = 0; mt < 4; mt++) {
        int nr0 = n0 + warp_m * 64 + mt * 16 + g;
        int nr1 = nr0 + 8;
        #pragma unroll
        for (int nt = 0; nt < 2; nt++) {
            int gm = m0 + warp_n * 16 + nt * 8 + 2 * tg;
            float2 mk0 = *(const float2*)&mask[((size_t)b * Nn + nr0) * Mm + gm];
            float2 mk1 = *(const float2*)&mask[((size_t)b * Nn + nr1) * Mm + gm];
            float p0 = (mk0.x > 0.f) ? __expf(acc[mt][nt][0] * 0.125f) : 0.f;
            float p1 = (mk0.y > 0.f) ? __expf(acc[mt][nt][1] * 0.125f) : 0.f;
            float p2 = (mk1.x > 0.f) ? __expf(acc[mt][nt][2] * 0.125f) : 0.f;
            float p3 = (mk1.y > 0.f) ? __expf(acc[mt][nt][3] * 0.125f) : 0.f;
            uint32_t hh, ll;
            size_t base0 = ((size_t)bh * Nn + nr0) * (Mm / 2) + (gm >> 1);
            size_t base1 = ((size_t)bh * Nn + nr1) * (Mm / 2) + (gm >> 1);
            pack_split(p0, p1, hh, ll); g_ph[base0] = hh; g_pl[base0] = ll;
            pack_split(p2, p3, hh, ll); g_ph[base1] = hh; g_pl[base1] = ll;
            rsum[mt][0] += p0 + p1;
            rsum[mt][1] += p2 + p3;
        }
    }
    #pragma unroll
    for (int mt = 0; mt < 4; mt++)
        #pragma unroll
        for (int r = 0; r < 2; r++) {
            rsum[mt][r] += __shfl_xor_sync(0xffffffffu, rsum[mt][r], 1);
            rsum[mt][r] += __shfl_xor_sync(0xffffffffu, rsum[mt][r], 2);
        }
    if (tg == 0) {
        #pragma unroll
        for (int mt = 0; mt < 4; mt++) {
            int rl = warp_m * 64 + mt * 16 + g;
            RED[warp_n * 128 + rl    ] = rsum[mt][0];
            RED[warp_n * 128 + rl + 8] = rsum[mt][1];
        }
    }
    __syncthreads();
    if (tid < 128) {
        float s = RED[tid] + RED[128 + tid] + RED[256 + tid] + RED[384 + tid];
        g_psum[((size_t)bh * Nn + n0 + tid) * 32 + blockIdx.x] = s;
    }
}

// ---------------------------------------------------------------------------
// Row-sum reduce: g_rowsum[row] = sum of 32 partials. 32768 rows.
// ---------------------------------------------------------------------------
__global__ void __launch_bounds__(256)
rowsum_reduce()
{
    int row = blockIdx.x * 256 + threadIdx.x;
    const float4* p = (const float4*)(g_psum + (size_t)row * 32);
    float s = 0.f;
    #pragma unroll
    for (int i = 0; i < 8; i++) {
        float4 v = p[i];
        s += v.x + v.y + v.z + v.w;
    }
    g_rowsum[row] = s;
}

// ---------------------------------------------------------------------------
// PV (bf16 3-term): msg[b,d*4+h,n] = (sum_m P_unnorm[bh,n,m]*v[..,m]) / rowsum[n]
// Block 64(d) x 128(n); m streamed in chunks of 32. P loaded pre-packed.
// ---------------------------------------------------------------------------
__global__ void __launch_bounds__(256)
attn_pv_mma()
{
    __shared__ uint32_t VHs[64][GST],  VLs[64][GST];    // [d][m-pair]
    __shared__ uint32_t PHs[128][GST], PLs[128][GST];   // [n][m-pair]

    const int tid = threadIdx.x;
    const int n0 = blockIdx.x * 128;
    const int bh = blockIdx.z;
    const int b = bh >> 2, h = bh & 3;
    const float* vg = g_v + (size_t)b * Dd * Mm;
    const uint32_t* PHg = g_ph + (size_t)bh * Nn * (Mm / 2);
    const uint32_t* PLg = g_pl + (size_t)bh * Nn * (Mm / 2);

    const int w      = tid >> 5;
    const int lane   = tid & 31;
    const int g      = lane >> 2;
    const int tg     = lane & 3;
    const int warp_m = w >> 2;   // d half
    const int warp_n = w & 3;

    float acc[2][4][4] = {};

    const int vd = tid >> 2;          // 0..63
    const int vq = tid & 3;           // 8 m each
    const int pn = tid >> 1;          // 0..127
    const int ph = tid & 1;           // 8 u32 each

    for (int m0 = 0; m0 < Mm; m0 += 32) {
        // V tile: VHs/L[d][mp]
        {
            const float* vp = vg + (size_t)(vd * Hh + h) * Mm + m0 + vq * 8;
            float4 u = *(const float4*)(vp);
            float4 v4 = *(const float4*)(vp + 4);
            uint4 hh, ll;
            pack_split(u.x,  u.y,  hh.x, ll.x);
            pack_split(u.z,  u.w,  hh.y, ll.y);
            pack_split(v4.x, v4.y, hh.z, ll.z);
            pack_split(v4.z, v4.w, hh.w, ll.w);
            *(uint4*)&VHs[vd][vq * 4] = hh;
            *(uint4*)&VLs[vd][vq * 4] = ll;
        }
        // P tile: direct u32 loads (already packed)
        {
            size_t base = (size_t)(n0 + pn) * (Mm / 2) + (m0 >> 1) + ph * 8;
            uint4 h0 = *(const uint4*)(PHg + base);
            uint4 h1 = *(const uint4*)(PHg + base + 4);
            uint4 l0 = *(const uint4*)(PLg + base);
            uint4 l1 = *(const uint4*)(PLg + base + 4);
            *(uint4*)&PHs[pn][ph * 8    ] = h0;
            *(uint4*)&PHs[pn][ph * 8 + 4] = h1;
            *(uint4*)&PLs[pn][ph * 8    ] = l0;
            *(uint4*)&PLs[pn][ph * 8 + 4] = l1;
        }
        __syncthreads();

        #pragma unroll
        for (int st = 0; st < 2; st++) {
            const int kc = st * 8;
            uint32_t ah[2][4], al[2][4], bh2[4][2], bl2[4][2];
            #pragma unroll
            for (int mt = 0; mt < 2; mt++) {
                int d = warp_m * 32 + mt * 16;
                ah[mt][0]=VHs[d+g  ][kc+tg  ]; al[mt][0]=VLs[d+g  ][kc+tg  ];
                ah[mt][1]=VHs[d+g+8][kc+tg  ]; al[mt][1]=VLs[d+g+8][kc+tg  ];
                ah[mt][2]=VHs[d+g  ][kc+tg+4]; al[mt][2]=VLs[d+g  ][kc+tg+4];
                ah[mt][3]=VHs[d+g+8][kc+tg+4]; al[mt][3]=VLs[d+g+8][kc+tg+4];
            }
            #pragma unroll
            for (int nt = 0; nt < 4; nt++) {
                int n = warp_n * 32 + nt * 8 + g;
                bh2[nt][0]=PHs[n][kc+tg  ]; bl2[nt][0]=PLs[n][kc+tg  ];
                bh2[nt][1]=PHs[n][kc+tg+4]; bl2[nt][1]=PLs[n][kc+tg+4];
            }
            #pragma unroll
            for (int mt = 0; mt < 2; mt++)
                #pragma unroll
                for (int nt = 0; nt < 4; nt++)
                    mma3(acc[mt][nt], ah[mt], al[mt], bh2[nt], bl2[nt]);
        }
        __syncthreads();
    }

    const float* rs = g_rowsum + (size_t)bh * Nn + n0;
    float* mp = g_msg + (size_t)b * Dd * Nn;
    #pragma unroll
    for (int mt = 0; mt < 2; mt++) {
        int d0 = warp_m * 32 + mt * 16 + g;
        int d1 = d0 + 8;
        #pragma unroll
        for (int nt = 0; nt < 4; nt++) {
            int n = warp_n * 32 + nt * 8 + 2 * tg;
            float inv0 = 1.f / rs[n];
            float inv1 = 1.f / rs[n + 1];
            *(float2*)&mp[(size_t)(d0 * Hh + h) * Nn + n0 + n] =
                make_float2(acc[mt][nt][0] * inv0, acc[mt][nt][1] * inv1);
            *(float2*)&mp[(size_t)(d1 * Hh + h) * Nn + n0 + n] =
                make_float2(acc[mt][nt][2] * inv0, acc[mt][nt][3] * inv1);
        }
    }
}

// ---------------------------------------------------------------------------
extern "C" void kernel_launch(void* const* d_in, const int* in_sizes, int n_in,
                              void* d_out, int out_size)
{
    const float* x      = (const float*)d_in[0];
    const float* source = (const float*)d_in[1];
    const float* mask   = (const float*)d_in[2];
    const float* Wq = (const float*)d_in[3];
    const float* bq = (const float*)d_in[4];
    const float* Wk = (const float*)d_in[5];
    const float* bk = (const float*)d_in[6];
    const float* Wv = (const float*)d_in[7];
    const float* bv = (const float*)d_in[8];
    const float* Wm = (const float*)d_in[9];
    const float* bm = (const float*)d_in[10];
    const float* W1 = (const float*)d_in[11];
    const float* b1 = (const float*)d_in[12];
    const float* gamma = (const float*)d_in[13];
    const float* beta  = (const float*)d_in[14];
    const float* rmean = (const float*)d_in[15];
    const float* rvar  = (const float*)d_in[16];
    const float* W2 = (const float*)d_in[17];
    const float* b2 = (const float*)d_in[18];
    float* out = (float*)d_out;

    float *qb, *kb, *vb, *msgb, *messageb, *hb;
    cudaGetSymbolAddress((void**)&qb, g_q);
    cudaGetSymbolAddress((void**)&kb, g_k);
    cudaGetSymbolAddress((void**)&vb, g_v);
    cudaGetSymbolAddress((void**)&msgb, g_msg);
    cudaGetSymbolAddress((void**)&messageb, g_message);
    cudaGetSymbolAddress((void**)&hb, g_h);

    const int SMEM_SCORES = (2 * 128 * AST + 2 * 64 * AST + 512) * 4;  // 57344 B
    cudaFuncSetAttribute(attn_scores_p,
                         cudaFuncAttributeMaxDynamicSharedMemorySize, SMEM_SCORES);

    // q, k, v projections
    gemm_mma<256, 256, false, false><<<dim3(16, 4, 4), 256>>>(
        Wq, bq, x, nullptr, qb, nullptr, nullptr, nullptr, nullptr);
    gemm_mma<256, 256, false, false><<<dim3(16, 4, 4), 256>>>(
        Wk, bk, source, nullptr, kb, nullptr, nullptr, nullptr, nullptr);
    gemm_mma<256, 256, false, false><<<dim3(16, 4, 4), 256>>>(
        Wv, bv, source, nullptr, vb, nullptr, nullptr, nullptr, nullptr);

    // attention: P_unnorm + partial sums, reduce, PV with normalization
    attn_scores_p<<<dim3(32, 16, 16), 256, SMEM_SCORES>>>(mask);
    rowsum_reduce<<<128, 256>>>();
    attn_pv_mma<<<dim3(16, 1, 16), 256>>>();

    // message projection
    gemm_mma<256, 256, false, false><<<dim3(16, 4, 4), 256>>>(
        Wm, bm, msgb, nullptr, messageb, nullptr, nullptr, nullptr, nullptr);

    // MLP layer 1 (concat[x, message]) + BN + ReLU
    gemm_mma<512, 512, true, true><<<dim3(16, 8, 4), 256>>>(
        W1, b1, x, messageb, hb, gamma, beta, rmean, rvar);

    // MLP layer 2 -> output
    gemm_mma<256, 512, false, false><<<dim3(16, 4, 4), 256>>>(
        W2, b2, hb, nullptr, out, nullptr, nullptr, nullptr, nullptr);
}